// round 15
// baseline (speedup 1.0000x reference)
#include <cuda_runtime.h>
#include <cuda_fp16.h>
#include <math.h>
#include <stdint.h>

#define CDIV(a,b) (((a)+(b)-1)/(b))

__device__ __forceinline__ float gelu_f(float x){
  const float c0 = 0.7978845608028654f;
  return 0.5f*x*(1.f + tanhf(c0*(x + 0.044715f*x*x*x)));
}
__device__ __forceinline__ void mma16816(float* d, const uint32_t* a, const uint32_t* b){
  asm volatile(
    "mma.sync.aligned.m16n8k16.row.col.f32.f16.f16.f32 "
    "{%0,%1,%2,%3}, {%4,%5,%6,%7}, {%8,%9}, {%0,%1,%2,%3};"
    : "+f"(d[0]), "+f"(d[1]), "+f"(d[2]), "+f"(d[3])
    : "r"(a[0]), "r"(a[1]), "r"(a[2]), "r"(a[3]), "r"(b[0]), "r"(b[1]));
}
__device__ __forceinline__ void ldm4(uint32_t* r, uint32_t addr){
  asm volatile("ldmatrix.sync.aligned.m8n8.x4.shared.b16 {%0,%1,%2,%3}, [%4];"
    : "=r"(r[0]), "=r"(r[1]), "=r"(r[2]), "=r"(r[3]) : "r"(addr));
}
__device__ __forceinline__ uint32_t smem_u32(const void* p){
  uint32_t a;
  asm("{ .reg .u64 t; cvta.to.shared.u64 t, %1; cvt.u32.u64 %0, t; }" : "=r"(a) : "l"(p));
  return a;
}
__device__ __forceinline__ void cp16(uint32_t dst, const void* src, int sz){
  asm volatile("cp.async.cg.shared.global [%0], [%1], 16, %2;"
               :: "r"(dst), "l"(src), "r"(sz) : "memory");
}
__device__ __forceinline__ void split_hf(float v, __half& h, __half& l){
  h = __float2half_rn(v);
  l = __float2half_rn(v - __half2float(h));
}
__device__ __forceinline__ uint32_t pack2h(__half a, __half b){
  __half2 t(a,b);
  return *reinterpret_cast<uint32_t*>(&t);
}
__device__ __forceinline__ uint32_t cvt_h2(float a, float b){
  uint32_t r; asm("cvt.rn.f16x2.f32 %0, %1, %2;" : "=r"(r) : "f"(b), "f"(a)); return r;
}
// packed dual-fp32 FMA
__device__ __forceinline__ uint64_t pk2f(float lo, float hi){
  uint64_t r; asm("mov.b64 %0, {%1,%2};" : "=l"(r) : "f"(lo), "f"(hi)); return r;
}
__device__ __forceinline__ void fma2(uint64_t& d, uint64_t a, uint64_t b){
  asm("fma.rn.f32x2 %0, %1, %2, %0;" : "+l"(d) : "l"(a), "l"(b));
}
__device__ __forceinline__ void unpk2f(uint64_t v, float& lo, float& hi){
  asm("mov.b64 {%0,%1}, %2;" : "=f"(lo), "=f"(hi) : "l"(v));
}

// ================= device scratch =================
__device__ float g_c1[64*8*1800];
__device__ __half g_a1h[64*8*1800], g_a1l[64*8*1800];
__device__ __half g_col2h[11520*808], g_col2l[11520*808];
__device__ float g_c2g[11520*80];
__device__ __half g_a2h[11520*80], g_a2l[11520*80];
__device__ __half g_col3h[1152*4080], g_col3l[1152*4080];
__device__ float g_c3[1152*800];
__device__ float g_x[1152*800];
__device__ __half g_xh[1152*800], g_xl[1152*800];
__device__ float g_qkv[1152*2400];
__device__ __half g_atth[1152*800], g_attl[1152*800];
__device__ __half g_hh[1152*3200], g_hl[1152*3200];
__device__ float g_part[3*1152*800];
__device__ float g_stats[128];
// weights: single fp16
__device__ __half g_w2[80*808];
__device__ __half g_w3[800*4080];
__device__ __half g_wip[8*2400*800];
__device__ __half g_wao[8*800*800];
__device__ __half g_wl1[8*3200*800];
__device__ __half g_wl2[8*800*3200];
__device__ __half g_wout[800*800];

// ================= merged weight conversion =================
struct WConvArgs {
  const float4* s[7];
  uint4* h[7];
  int n8[7];
};
__global__ __launch_bounds__(256) void wconv_all(WConvArgs a)
{
  const int gid = blockIdx.x*256 + threadIdx.x;
  const int stride = gridDim.x*256;
  #pragma unroll 1
  for (int si = 0; si < 7; ++si) {
    const float4* __restrict__ S = a.s[si];
    uint4* __restrict__ H = a.h[si];
    const int n = a.n8[si];
    for (int i = gid; i < n; i += stride) {
      float4 x = S[2*i], y = S[2*i+1];
      H[i] = make_uint4(cvt_h2(x.x,x.y), cvt_h2(x.z,x.w),
                        cvt_h2(y.x,y.y), cvt_h2(y.z,y.w));
    }
  }
}

#define PADK 40
#define ALOFF (64u*PADK*2)
#define BOFF  (128u*PADK*2)
#define STAGE4_BYTES (256*PADK*2)   // 20480
#define GEMM4_SMEM (2*STAGE4_BYTES) // 40960 (2-stage: confirmed optimal)

// OUTBF: 0=fp32+bias(+ACT), 1=fp16 hi/lo+bias(+ACT), 2=raw fp32 partial (split-K via gridDim.z)
template<int ACT, int OUTBF>
__global__ void __launch_bounds__(256) gemm4(
    const __half* __restrict__ Ah, const __half* __restrict__ Al,
    const __half* __restrict__ B,
    const float* __restrict__ bias, float* __restrict__ C,
    __half* __restrict__ Ch, __half* __restrict__ Cl,
    int M, int N, int K)
{
  extern __shared__ __align__(16) __half sm[];
  const int tid = threadIdx.x;
  const int wid = tid >> 5;
  const int lane = tid & 31;
  const int g = lane >> 2;
  const int t2 = (lane & 3) * 2;
  const int wm = wid >> 2;
  const int wn = wid & 3;
  const int bm = blockIdx.y * 64;
  const int bn = blockIdx.x * 128;
  const uint32_t smb = smem_u32(sm);

  const int j8 = lane >> 3, lr = lane & 7;
  const uint32_t offA0 = (uint32_t)((wm*32 + 0*16 + (j8&1)*8 + lr)*PADK + (j8>>1)*8)*2;
  const uint32_t offA1 = (uint32_t)((wm*32 + 1*16 + (j8&1)*8 + lr)*PADK + (j8>>1)*8)*2;
  const uint32_t offB0 = (uint32_t)((wn*32 + 0*16 + (j8>>1)*8 + lr)*PADK + (j8&1)*8)*2;
  const uint32_t offB1 = (uint32_t)((wn*32 + 1*16 + (j8>>1)*8 + lr)*PADK + (j8&1)*8)*2;

  float acc[2][4][4];
  #pragma unroll
  for (int i=0;i<2;++i)
    #pragma unroll
    for (int jj=0;jj<4;++jj)
      #pragma unroll
      for (int k=0;k<4;++k) acc[i][jj][k]=0.f;

  const int nst   = CDIV(K, 32);
  const int chunk = CDIV(nst, (int)gridDim.z);
  const int sbeg  = blockIdx.z * chunk;
  const int send  = min(nst, sbeg + chunk);

  auto load_stage = [&](int s){
    const uint32_t base = smb + (uint32_t)(s & 1) * STAGE4_BYTES;
    const int k0 = s * 32;
    {
      int r = tid >> 2, c = (tid & 3) * 8;
      uint32_t d = base + (uint32_t)(r*PADK + c)*2;
      int gk = k0 + c;
      int sz = (gk < K) ? 16 : 0;
      size_t off = (size_t)(bm + r)*K + (sz ? gk : 0);
      cp16(d,         Ah + off, sz);
      cp16(d + ALOFF, Al + off, sz);
    }
    #pragma unroll
    for (int jj = 0; jj < 2; ++jj) {
      int sid = tid + jj*256;
      int r = sid >> 2, c = (sid & 3) * 8;
      uint32_t d = base + BOFF + (uint32_t)(r*PADK + c)*2;
      int gk = k0 + c;
      int rb = bn + r;
      int sz = (rb < N && gk < K) ? 16 : 0;
      size_t off = (size_t)(sz ? rb : 0)*K + (sz ? gk : 0);
      cp16(d, B + off, sz);
    }
    asm volatile("cp.async.commit_group;" ::: "memory");
  };

  load_stage(sbeg);

  for (int s = sbeg; s < send; ++s) {
    if (s + 1 < send) {
      load_stage(s + 1);
      asm volatile("cp.async.wait_group 1;" ::: "memory");
    } else {
      asm volatile("cp.async.wait_group 0;" ::: "memory");
    }
    __syncthreads();

    const uint32_t stA = smb + (uint32_t)(s & 1) * STAGE4_BYTES;
    const uint32_t stB = stA + BOFF;

    #pragma unroll
    for (int ks = 0; ks < 32; ks += 16) {
      const uint32_t kd = (uint32_t)ks * 2;
      uint32_t ah0[4], ah1[4], al0[4], al1[4], bq0[4], bq1[4];
      ldm4(ah0, stA + offA0 + kd);
      ldm4(ah1, stA + offA1 + kd);
      ldm4(al0, stA + ALOFF + offA0 + kd);
      ldm4(al1, stA + ALOFF + offA1 + kd);
      ldm4(bq0, stB + offB0 + kd);
      ldm4(bq1, stB + offB1 + kd);

      const uint32_t* bf[4] = { &bq0[0], &bq0[2], &bq1[0], &bq1[2] };
      uint32_t* ah[2] = { ah0, ah1 };
      uint32_t* al[2] = { al0, al1 };

      #pragma unroll
      for (int mf = 0; mf < 2; ++mf)
        #pragma unroll
        for (int nf = 0; nf < 4; ++nf) {
          mma16816(acc[mf][nf], ah[mf], bf[nf]);
          mma16816(acc[mf][nf], al[mf], bf[nf]);
        }
    }
    __syncthreads();
  }

  float* Cz = (OUTBF == 2) ? (C + (size_t)blockIdx.z * M * N) : C;

  #pragma unroll
  for (int mf = 0; mf < 2; ++mf) {
    int row0 = bm + wm*32 + mf*16 + g;
    #pragma unroll
    for (int nf = 0; nf < 4; ++nf) {
      int col = bn + wn*32 + nf*8 + t2;
      if (col >= N) continue;
      if (OUTBF == 2) {
        if (col+1 < N) {
          *(float2*)(Cz + (size_t)row0*N + col)     = make_float2(acc[mf][nf][0], acc[mf][nf][1]);
          *(float2*)(Cz + (size_t)(row0+8)*N + col) = make_float2(acc[mf][nf][2], acc[mf][nf][3]);
        } else {
          Cz[(size_t)row0*N + col]     = acc[mf][nf][0];
          Cz[(size_t)(row0+8)*N + col] = acc[mf][nf][2];
        }
        continue;
      }
      float b0 = bias[col];
      float b1 = (col+1 < N) ? bias[col+1] : 0.f;
      float v0 = acc[mf][nf][0] + b0, v1 = acc[mf][nf][1] + b1;
      float v2 = acc[mf][nf][2] + b0, v3 = acc[mf][nf][3] + b1;
      if (ACT == 1) { v0=gelu_f(v0); v1=gelu_f(v1); v2=gelu_f(v2); v3=gelu_f(v3); }
      if (OUTBF == 0) {
        if (col+1 < N) {
          *(float2*)(Cz + (size_t)row0*N + col)     = make_float2(v0, v1);
          *(float2*)(Cz + (size_t)(row0+8)*N + col) = make_float2(v2, v3);
        } else {
          Cz[(size_t)row0*N + col] = v0;
          Cz[(size_t)(row0+8)*N + col] = v2;
        }
      } else {
        __half h0,l0,h1,l1;
        if (col+1 < N) {
          split_hf(v0,h0,l0); split_hf(v1,h1,l1);
          *(uint32_t*)(Ch + (size_t)row0*N + col) = pack2h(h0,h1);
          *(uint32_t*)(Cl + (size_t)row0*N + col) = pack2h(l0,l1);
          split_hf(v2,h0,l0); split_hf(v3,h1,l1);
          *(uint32_t*)(Ch + (size_t)(row0+8)*N + col) = pack2h(h0,h1);
          *(uint32_t*)(Cl + (size_t)(row0+8)*N + col) = pack2h(l0,l1);
        } else {
          split_hf(v0,h0,l0); Ch[(size_t)row0*N+col]=h0;     Cl[(size_t)row0*N+col]=l0;
          split_hf(v2,h0,l0); Ch[(size_t)(row0+8)*N+col]=h0; Cl[(size_t)(row0+8)*N+col]=l0;
        }
      }
    }
  }
}

// ===== split-K reduce (float4) =====
__global__ void red_plain(const float4* __restrict__ p, const float* __restrict__ bias,
                          float4* __restrict__ C, int MN4, int N, int nz)
{
  int i = blockIdx.x*256 + threadIdx.x;
  if (i >= MN4) return;
  int col = (i*4) % N;
  float4 v = *(const float4*)&bias[col];
  for (int z = 0; z < nz; ++z) {
    float4 pv = p[(size_t)z*MN4 + i];
    v.x += pv.x; v.y += pv.y; v.z += pv.z; v.w += pv.w;
  }
  C[i] = v;
}

// ===== split-K(2) reduce fused with residual add + LayerNorm (float4) =====
__global__ __launch_bounds__(256) void red_add_ln(float* __restrict__ x,
    __half* __restrict__ xh, __half* __restrict__ xl,
    const float* __restrict__ p, const float* __restrict__ bias,
    const float* __restrict__ g, const float* __restrict__ be)
{
  const int row = blockIdx.x;
  const int tid = threadIdx.x;
  const int MN4 = 1152*200;
  __shared__ float t[800];
  __shared__ float sh1[256], sh2[256];
  float s = 0.f, q = 0.f;
  if (tid < 200) {
    size_t o4 = (size_t)row*200 + tid;
    float4 xv = ((const float4*)x)[o4];
    float4 p0 = ((const float4*)p)[o4];
    float4 p1 = ((const float4*)p)[MN4 + o4];
    float4 bv = ((const float4*)bias)[tid];
    float v0 = xv.x + p0.x + p1.x + bv.x;
    float v1 = xv.y + p0.y + p1.y + bv.y;
    float v2 = xv.z + p0.z + p1.z + bv.z;
    float v3 = xv.w + p0.w + p1.w + bv.w;
    t[tid*4+0]=v0; t[tid*4+1]=v1; t[tid*4+2]=v2; t[tid*4+3]=v3;
    s = v0+v1+v2+v3;
    q = v0*v0+v1*v1+v2*v2+v3*v3;
  }
  sh1[tid] = s; sh2[tid] = q;
  __syncthreads();
  for (int st = 128; st > 0; st >>= 1) {
    if (tid < st) { sh1[tid] += sh1[tid+st]; sh2[tid] += sh2[tid+st]; }
    __syncthreads();
  }
  float m = sh1[0] / 800.f;
  float r = rsqrtf(sh2[0] / 800.f - m*m + 1e-5f);
  if (tid < 200) {
    float4 gv = ((const float4*)g)[tid];
    float4 bev = ((const float4*)be)[tid];
    float v0 = (t[tid*4+0]-m)*r*gv.x + bev.x;
    float v1 = (t[tid*4+1]-m)*r*gv.y + bev.y;
    float v2 = (t[tid*4+2]-m)*r*gv.z + bev.z;
    float v3 = (t[tid*4+3]-m)*r*gv.w + bev.w;
    size_t o4 = (size_t)row*200 + tid;
    ((float4*)x)[o4] = make_float4(v0,v1,v2,v3);
    __half h0,l0,h1,l1,h2,l2,h3,l3;
    split_hf(v0,h0,l0); split_hf(v1,h1,l1); split_hf(v2,h2,l2); split_hf(v3,h3,l3);
    ((uint2*)xh)[o4] = make_uint2(pack2h(h0,h1), pack2h(h2,h3));
    ((uint2*)xl)[o4] = make_uint2(pack2h(l0,l1), pack2h(l2,l3));
  }
}

// ================= conv1 (round-12 exact: f32x2, grid 64x4) =================
__global__ __launch_bounds__(128) void conv1_kernel(const float* __restrict__ src,
    const float* __restrict__ w, const float* __restrict__ bias, float* __restrict__ out)
{
  const int b  = blockIdx.x;
  const int l0 = blockIdx.y * 450;
  const int t  = threadIdx.x;
  __shared__ float s_in[2464];
  __shared__ float s_wt[1632];
  uint64_t acc2[4][4];
  #pragma unroll
  for (int j=0;j<4;++j)
    #pragma unroll
    for (int p=0;p<4;++p) acc2[j][p] = pk2f(0.f, 0.f);
  const int base = 5*l0 - 100;
  const int tc = (t < 112) ? t : 112;

  for (int i = 0; i < 12; ++i) {
    __syncthreads();
    for (int j = t; j < 2464; j += 128) {
      int p = base + j;
      s_in[j] = (p >= 0 && p < 9000) ? src[(size_t)(b*12+i)*9000 + p] : 0.f;
    }
    for (int j = t; j < 1632; j += 128) {
      int o = j & 7, k = j >> 3;
      s_wt[j] = (k < 201) ? w[(size_t)(o*12 + i)*201 + k] : 0.f;
    }
    __syncthreads();

    for (int k0 = 0; k0 < 201; k0 += 4) {
      float buf[24];
      {
        const float4* p4 = (const float4*)&s_in[20*tc + k0];
        #pragma unroll
        for (int q=0;q<6;++q) {
          float4 v = p4[q];
          buf[4*q]=v.x; buf[4*q+1]=v.y; buf[4*q+2]=v.z; buf[4*q+3]=v.w;
        }
      }
      uint64_t wr2[4][4];
      #pragma unroll
      for (int kk=0;kk<4;++kk) {
        float4 a = *(const float4*)&s_wt[(k0+kk)*8];
        float4 c = *(const float4*)&s_wt[(k0+kk)*8+4];
        wr2[kk][0]=pk2f(a.x,a.y); wr2[kk][1]=pk2f(a.z,a.w);
        wr2[kk][2]=pk2f(c.x,c.y); wr2[kk][3]=pk2f(c.z,c.w);
      }
      #pragma unroll
      for (int j=0;j<4;++j)
        #pragma unroll
        for (int kk=0;kk<4;++kk) {
          float in = buf[5*j+kk];
          uint64_t in2 = pk2f(in, in);
          #pragma unroll
          for (int p=0;p<4;++p) fma2(acc2[j][p], in2, wr2[kk][p]);
        }
    }
  }

  if (t <= 112) {
    #pragma unroll
    for (int j=0;j<4;++j) {
      int lt = 4*t + j;
      if (lt < 450) {
        int l = l0 + lt;
        #pragma unroll
        for (int p=0;p<4;++p) {
          float lo, hi;
          unpk2f(acc2[j][p], lo, hi);
          out[(size_t)(b*8 + 2*p    )*1800 + l] = lo + bias[2*p];
          out[(size_t)(b*8 + 2*p + 1)*1800 + l] = hi + bias[2*p+1];
        }
      }
    }
  }
}

// ================= GroupNorm(1) stats =================
__global__ __launch_bounds__(256) void gn_stats_kernel(const float* __restrict__ x,
                                                       float* __restrict__ stats, int n)
{
  const int b = blockIdx.x;
  const float* xb = x + (size_t)b * n;
  float s = 0.f, q = 0.f;
  for (int i = threadIdx.x; i < n; i += 256) { float v = xb[i]; s += v; q += v*v; }
  __shared__ float sh1[256], sh2[256];
  sh1[threadIdx.x] = s; sh2[threadIdx.x] = q;
  __syncthreads();
  for (int st = 128; st > 0; st >>= 1) {
    if (threadIdx.x < st) { sh1[threadIdx.x] += sh1[threadIdx.x+st]; sh2[threadIdx.x] += sh2[threadIdx.x+st]; }
    __syncthreads();
  }
  if (threadIdx.x == 0) {
    float m = sh1[0] / n;
    float v = sh2[0] / n - m*m;
    stats[2*b]   = m;
    stats[2*b+1] = rsqrtf(v + 1e-5f);
  }
}

// ===== GN1 apply + GELU + split (float4) =====
__global__ void gn1_apply_split(const float* __restrict__ c1,
    __half* __restrict__ ah, __half* __restrict__ al,
    const float* __restrict__ stats, const float* __restrict__ g, const float* __restrict__ be)
{
  int i4 = blockIdx.x*256 + threadIdx.x;
  if (i4 >= 64*8*450) return;
  int idx = i4*4;
  int b = idx / 14400;
  int i = (idx / 1800) & 7;
  float m = stats[2*b], r = stats[2*b+1];
  float gg = g[i], bb = be[i];
  float4 v4 = ((const float4*)c1)[i4];
  float v0 = gelu_f((v4.x-m)*r*gg + bb);
  float v1 = gelu_f((v4.y-m)*r*gg + bb);
  float v2 = gelu_f((v4.z-m)*r*gg + bb);
  float v3 = gelu_f((v4.w-m)*r*gg + bb);
  __half h0,l0,h1,l1,h2,l2,h3,l3;
  split_hf(v0,h0,l0); split_hf(v1,h1,l1); split_hf(v2,h2,l2); split_hf(v3,h3,l3);
  ((uint2*)ah)[i4] = make_uint2(pack2h(h0,h1), pack2h(h2,h3));
  ((uint2*)al)[i4] = make_uint2(pack2h(l0,l1), pack2h(l2,l3));
}

// ===== im2col2 gather =====
__global__ __launch_bounds__(256) void im2col2_gather(
    const __half* __restrict__ ah, const __half* __restrict__ al,
    __half* __restrict__ colh, __half* __restrict__ coll)
{
  const int l = blockIdx.x;
  const int b = blockIdx.y;
  const size_t rowo = ((size_t)(b*180 + l))*808;
  const int p0 = 10*l - 50;
  for (int c = threadIdx.x; c < 808; c += 256) {
    int i = c / 101;
    int kk = c - 101*i;
    int p = p0 + kk;
    __half h = __float2half(0.f), lo = __float2half(0.f);
    if (p >= 0 && p < 1800) {
      size_t src = (size_t)(b*8+i)*1800 + p;
      h = ah[src]; lo = al[src];
    }
    colh[rowo + c] = h; coll[rowo + c] = lo;
  }
}

// ===== GN2 apply + GELU + split (float4) =====
__global__ void gn2_apply_split(const float* __restrict__ c2g,
    __half* __restrict__ ah, __half* __restrict__ al,
    const float* __restrict__ stats, const float* __restrict__ g, const float* __restrict__ be)
{
  int i4 = blockIdx.x*256 + threadIdx.x;
  if (i4 >= 11520*20) return;
  int idx = i4*4;
  int b = idx / (180*80);
  int i0 = idx % 80;
  float m = stats[2*b], r = stats[2*b+1];
  float4 gv = *(const float4*)&g[i0];
  float4 bv = *(const float4*)&be[i0];
  float4 v4 = ((const float4*)c2g)[i4];
  float v0 = gelu_f((v4.x-m)*r*gv.x + bv.x);
  float v1 = gelu_f((v4.y-m)*r*gv.y + bv.y);
  float v2 = gelu_f((v4.z-m)*r*gv.z + bv.z);
  float v3 = gelu_f((v4.w-m)*r*gv.w + bv.w);
  __half h0,l0,h1,l1,h2,l2,h3,l3;
  split_hf(v0,h0,l0); split_hf(v1,h1,l1); split_hf(v2,h2,l2); split_hf(v3,h3,l3);
  ((uint2*)ah)[i4] = make_uint2(pack2h(h0,h1), pack2h(h2,h3));
  ((uint2*)al)[i4] = make_uint2(pack2h(l0,l1), pack2h(l2,l3));
}

// ===== im2col3 gather =====
__global__ __launch_bounds__(256) void im2col3_gather(
    const __half* __restrict__ ah, const __half* __restrict__ al,
    __half* __restrict__ colh, __half* __restrict__ coll)
{
  const int l = blockIdx.x;
  const int b = blockIdx.y;
  const size_t rowo = ((size_t)(b*18 + l))*4080;
  const int p0 = 10*l - 25;
  for (int c = threadIdx.x; c < 4080; c += 256) {
    int i = c / 51;
    int k = c - 51*i;
    int p = p0 + k;
    __half h = __float2half(0.f), lo = __float2half(0.f);
    if (p >= 0 && p < 180) {
      size_t src = (size_t)(b*180+p)*80 + i;
      h = ah[src]; lo = al[src];
    }
    colh[rowo + c] = h; coll[rowo + c] = lo;
  }
}

// GN3 + GELU + PE (float4)
__global__ void gn3_pe_kernel(const float* __restrict__ x, float* __restrict__ y,
    __half* __restrict__ yh, __half* __restrict__ yl,
    const float* __restrict__ stats, const float* __restrict__ g, const float* __restrict__ be)
{
  int i4 = blockIdx.x*blockDim.x + threadIdx.x;
  if (i4 >= 1152*200) return;
  int idx = i4*4;
  int row = idx / 800, d0 = idx % 800;
  int b = row / 18, s = row % 18;
  float m = stats[2*b], r = stats[2*b+1];
  float4 gv = *(const float4*)&g[d0];
  float4 bv = *(const float4*)&be[d0];
  float4 v4 = ((const float4*)x)[i4];
  float vv[4] = {
    gelu_f((v4.x-m)*r*gv.x + bv.x),
    gelu_f((v4.y-m)*r*gv.y + bv.y),
    gelu_f((v4.z-m)*r*gv.z + bv.z),
    gelu_f((v4.w-m)*r*gv.w + bv.w)
  };
  #pragma unroll
  for (int q = 0; q < 4; ++q) {
    int d = d0 + q;
    int de = d & ~1;
    float freq = expf((float)de * (-9.210340371976184f/800.f));
    float ang = (float)s * freq;
    vv[q] += (d & 1) ? cosf(ang) : sinf(ang);
  }
  ((float4*)y)[i4] = make_float4(vv[0],vv[1],vv[2],vv[3]);
  __half h0,l0,h1,l1,h2,l2,h3,l3;
  split_hf(vv[0],h0,l0); split_hf(vv[1],h1,l1); split_hf(vv[2],h2,l2); split_hf(vv[3],h3,l3);
  ((uint2*)yh)[i4] = make_uint2(pack2h(h0,h1), pack2h(h2,h3));
  ((uint2*)yl)[i4] = make_uint2(pack2h(l0,l1), pack2h(l2,l3));
}

// ================= attention (vectorized) =================
__global__ __launch_bounds__(128) void attn_kernel(const float* __restrict__ qkv,
    __half* __restrict__ outh, __half* __restrict__ outl)
{
  const int b = blockIdx.x, h = blockIdx.y;
  const int tid = threadIdx.x;
  __shared__ float sq[1800], sk[1800], sv[1800], sc[324];
  const float4* qkv4 = (const float4*)qkv;
  for (int idx = tid; idx < 450; idx += 128) {
    int s = idx / 25, d4 = idx % 25;
    size_t base = (size_t)(b*18+s)*600 + h*25 + d4;
    *(float4*)&sq[s*100 + d4*4] = qkv4[base];
    *(float4*)&sk[s*100 + d4*4] = qkv4[base + 200];
    *(float4*)&sv[s*100 + d4*4] = qkv4[base + 400];
  }
  __syncthreads();
  for (int p = tid; p < 324; p += 128) {
    int i = p/18, j = p%18;
    float dot = 0.f;
    #pragma unroll 4
    for (int d = 0; d < 100; ++d) dot = fmaf(sq[i*100+d], sk[j*100+d], dot);
    int di = i - j; if (di < 0) di = -di;
    float bias = (di > 2 && i != 0 && j != 0) ? -1e30f : 0.f;
    sc[p] = dot * 0.1f + bias;
  }
  __syncthreads();
  if (tid < 18) {
    float mx = -1e30f;
    for (int j = 0; j < 18; ++j) mx = fmaxf(mx, sc[tid*18+j]);
    float sum = 0.f;
    for (int j = 0; j < 18; ++j) { float e = expf(sc[tid*18+j]-mx); sc[tid*18+j] = e; sum += e; }
    float inv = 1.f/sum;
    for (int j = 0; j < 18; ++j) sc[tid*18+j] *= inv;
  }
  __syncthreads();
  for (int idx = tid; idx < 450; idx += 128) {
    int i = idx / 25, d4 = idx % 25;
    float o0=0.f,o1=0.f,o2=0.f,o3=0.f;
    #pragma unroll
    for (int j = 0; j < 18; ++j) {
      float wgt = sc[i*18+j];
      float4 v = *(const float4*)&sv[j*100 + d4*4];
      o0 = fmaf(wgt, v.x, o0); o1 = fmaf(wgt, v.y, o1);
      o2 = fmaf(wgt, v.z, o2); o3 = fmaf(wgt, v.w, o3);
    }
    size_t o4 = ((size_t)(b*18+i)*800 + h*100 + d4*4) >> 2;
    __half h0,l0,h1,l1,h2,l2,h3,l3;
    split_hf(o0,h0,l0); split_hf(o1,h1,l1); split_hf(o2,h2,l2); split_hf(o3,h3,l3);
    ((uint2*)outh)[o4] = make_uint2(pack2h(h0,h1), pack2h(h2,h3));
    ((uint2*)outl)[o4] = make_uint2(pack2h(l0,l1), pack2h(l2,l3));
  }
}

// ================= host =================
static float* symf(const void* s){ void* p; cudaGetSymbolAddress(&p, s); return (float*)p; }
static __half* symh(const void* s){ void* p; cudaGetSymbolAddress(&p, s); return (__half*)p; }

extern "C" void kernel_launch(void* const* d_in, const int* in_sizes, int n_in,
                              void* d_out, int out_size)
{
  const float* src        = (const float*)d_in[0];
  const float* cw1        = (const float*)d_in[1];
  const float* cb1        = (const float*)d_in[2];
  const float* gn1_g      = (const float*)d_in[3];
  const float* gn1_b      = (const float*)d_in[4];
  const float* cw2        = (const float*)d_in[5];
  const float* cb2        = (const float*)d_in[6];
  const float* gn2_g      = (const float*)d_in[7];
  const float* gn2_b      = (const float*)d_in[8];
  const float* cw3        = (const float*)d_in[9];
  const float* cb3        = (const float*)d_in[10];
  const float* gn3_g      = (const float*)d_in[11];
  const float* gn3_b      = (const float*)d_in[12];
  const float* in_proj_w  = (const float*)d_in[13];
  const float* in_proj_b  = (const float*)d_in[14];
  const float* attn_out_w = (const float*)d_in[15];
  const float* attn_out_b = (const float*)d_in[16];
  const float* lin1_w     = (const float*)d_in[17];
  const float* lin1_b     = (const float*)d_in[18];
  const float* lin2_w     = (const float*)d_in[19];
  const float* lin2_b     = (const float*)d_in[20];
  const float* ln1_g      = (const float*)d_in[21];
  const float* ln1_b      = (const float*)d_in[22];
  const float* ln2_g      = (const float*)d_in[23];
  const float* ln2_b      = (const float*)d_in[24];
  const float* out_w      = (const float*)d_in[25];
  const float* out_b      = (const float*)d_in[26];

  float* c1   = symf(g_c1);
  float* c2g  = symf(g_c2g);
  float* c3   = symf(g_c3);
  float* x    = symf(g_x);
  float* qkv  = symf(g_qkv);
  float* part = symf(g_part);
  float* st   = symf(g_stats);
  __half *a1h=symh(g_a1h), *a1l=symh(g_a1l);
  __half *a2h=symh(g_a2h), *a2l=symh(g_a2l);
  __half *col2h=symh(g_col2h), *col2l=symh(g_col2l);
  __half *col3h=symh(g_col3h), *col3l=symh(g_col3l);
  __half *xh=symh(g_xh), *xl=symh(g_xl);
  __half *atth=symh(g_atth), *attl=symh(g_attl);
  __half *hh=symh(g_hh), *hl=symh(g_hl);
  __half *w2=symh(g_w2), *w3=symh(g_w3), *wip=symh(g_wip), *wao=symh(g_wao);
  __half *wl1=symh(g_wl1), *wl2=symh(g_wl2), *wout=symh(g_wout);

  // one-time host-side setup (no device allocation)
  static cudaStream_t s2 = nullptr;
  static cudaEvent_t evF = nullptr, evJ = nullptr;
  if (!s2) {
    cudaStreamCreateWithFlags(&s2, cudaStreamNonBlocking);
    cudaEventCreateWithFlags(&evF, cudaEventDisableTiming);
    cudaEventCreateWithFlags(&evJ, cudaEventDisableTiming);
    cudaFuncSetAttribute(gemm4<0,0>, cudaFuncAttributeMaxDynamicSharedMemorySize, GEMM4_SMEM);
    cudaFuncSetAttribute(gemm4<1,1>, cudaFuncAttributeMaxDynamicSharedMemorySize, GEMM4_SMEM);
    cudaFuncSetAttribute(gemm4<0,2>, cudaFuncAttributeMaxDynamicSharedMemorySize, GEMM4_SMEM);
  }

  // ---- fork: weight conversion on side stream, overlapping patch-embed ----
  cudaEventRecord(evF, 0);
  cudaStreamWaitEvent(s2, evF, 0);
  {
    WConvArgs a;
    a.s[0]=(const float4*)cw2;        a.h[0]=(uint4*)w2;   a.n8[0]=80*808/8;
    a.s[1]=(const float4*)cw3;        a.h[1]=(uint4*)w3;   a.n8[1]=800*4080/8;
    a.s[2]=(const float4*)in_proj_w;  a.h[2]=(uint4*)wip;  a.n8[2]=8*2400*800/8;
    a.s[3]=(const float4*)attn_out_w; a.h[3]=(uint4*)wao;  a.n8[3]=8*800*800/8;
    a.s[4]=(const float4*)lin1_w;     a.h[4]=(uint4*)wl1;  a.n8[4]=8*3200*800/8;
    a.s[5]=(const float4*)lin2_w;     a.h[5]=(uint4*)wl2;  a.n8[5]=8*800*3200/8;
    a.s[6]=(const float4*)out_w;      a.h[6]=(uint4*)wout; a.n8[6]=800*800/8;
    wconv_all<<<1184,256,0,s2>>>(a);
  }
  cudaEventRecord(evJ, s2);

  // ---- patch embedding front-end (independent of weights) ----
  conv1_kernel<<<dim3(64,4),128>>>(src, cw1, cb1, c1);
  gn_stats_kernel<<<64,256>>>(c1, st, 8*1800);
  gn1_apply_split<<<CDIV(64*8*450,256),256>>>(c1, a1h, a1l, st, gn1_g, gn1_b);
  im2col2_gather<<<dim3(180,64),256>>>(a1h, a1l, col2h, col2l);

  // ---- join: weights ready before first GEMM ----
  cudaStreamWaitEvent(0, evJ, 0);

  gemm4<0,2><<<dim3(1,180,2),256,GEMM4_SMEM>>>(col2h, col2l, w2, nullptr, part,
                                               nullptr, nullptr, 11520, 80, 808);
  red_plain<<<CDIV(11520*20,256),256>>>((const float4*)part, cb2, (float4*)c2g, 11520*20, 80, 2);
  gn_stats_kernel<<<64,256>>>(c2g, st, 180*80);
  gn2_apply_split<<<CDIV(11520*20,256),256>>>(c2g, a2h, a2l, st, gn2_g, gn2_b);
  im2col3_gather<<<dim3(18,64),256>>>(a2h, a2l, col3h, col3l);
  gemm4<0,2><<<dim3(7,18,3),256,GEMM4_SMEM>>>(col3h, col3l, w3, nullptr, part,
                                              nullptr, nullptr, 1152, 800, 4080);
  red_plain<<<CDIV(1152*200,256),256>>>((const float4*)part, cb3, (float4*)c3, 1152*200, 800, 3);
  gn_stats_kernel<<<64,256>>>(c3, st, 18*800);
  gn3_pe_kernel<<<CDIV(1152*200,256),256>>>(c3, x, xh, xl, st, gn3_g, gn3_b);

  // ---- transformer layers ----
  for (int i = 0; i < 8; ++i) {
    gemm4<0,0><<<dim3(19,18),256,GEMM4_SMEM>>>(xh, xl,
        wip + (size_t)i*2400*800,
        in_proj_b + (size_t)i*2400, qkv, nullptr, nullptr, 1152, 2400, 800);
    attn_kernel<<<dim3(64,8),128>>>(qkv, atth, attl);
    gemm4<0,2><<<dim3(7,18,2),256,GEMM4_SMEM>>>(atth, attl,
        wao + (size_t)i*800*800,
        nullptr, part, nullptr, nullptr, 1152, 800, 800);
    red_add_ln<<<1152,256>>>(x, xh, xl, part, attn_out_b + (size_t)i*800,
                             ln1_g + (size_t)i*800, ln1_b + (size_t)i*800);
    gemm4<1,1><<<dim3(25,18),256,GEMM4_SMEM>>>(xh, xl,
        wl1 + (size_t)i*3200*800,
        lin1_b + (size_t)i*3200, nullptr, hh, hl, 1152, 3200, 800);
    gemm4<0,2><<<dim3(7,18,2),256,GEMM4_SMEM>>>(hh, hl,
        wl2 + (size_t)i*800*3200,
        nullptr, part, nullptr, nullptr, 1152, 800, 3200);
    red_add_ln<<<1152,256>>>(x, xh, xl, part, lin2_b + (size_t)i*800,
                             ln2_g + (size_t)i*800, ln2_b + (size_t)i*800);
  }

  // ---- output projection (split-K=2 + reduce into d_out) ----
  gemm4<0,2><<<dim3(7,18,2),256,GEMM4_SMEM>>>(xh, xl, wout, nullptr, part,
                                              nullptr, nullptr, 1152, 800, 800);
  red_plain<<<CDIV(1152*200,256),256>>>((const float4*)part, out_b, (float4*)d_out, 1152*200, 800, 2);
}

// round 16
// speedup vs baseline: 1.1364x; 1.1364x over previous
#include <cuda_runtime.h>
#include <cuda_fp16.h>
#include <math.h>
#include <stdint.h>

#define CDIV(a,b) (((a)+(b)-1)/(b))

__device__ __forceinline__ float gelu_f(float x){
  const float c0 = 0.7978845608028654f;
  return 0.5f*x*(1.f + tanhf(c0*(x + 0.044715f*x*x*x)));
}
__device__ __forceinline__ void mma16816(float* d, const uint32_t* a, const uint32_t* b){
  asm volatile(
    "mma.sync.aligned.m16n8k16.row.col.f32.f16.f16.f32 "
    "{%0,%1,%2,%3}, {%4,%5,%6,%7}, {%8,%9}, {%0,%1,%2,%3};"
    : "+f"(d[0]), "+f"(d[1]), "+f"(d[2]), "+f"(d[3])
    : "r"(a[0]), "r"(a[1]), "r"(a[2]), "r"(a[3]), "r"(b[0]), "r"(b[1]));
}
__device__ __forceinline__ void ldm4(uint32_t* r, uint32_t addr){
  asm volatile("ldmatrix.sync.aligned.m8n8.x4.shared.b16 {%0,%1,%2,%3}, [%4];"
    : "=r"(r[0]), "=r"(r[1]), "=r"(r[2]), "=r"(r[3]) : "r"(addr));
}
__device__ __forceinline__ uint32_t smem_u32(const void* p){
  uint32_t a;
  asm("{ .reg .u64 t; cvta.to.shared.u64 t, %1; cvt.u32.u64 %0, t; }" : "=r"(a) : "l"(p));
  return a;
}
__device__ __forceinline__ void cp16(uint32_t dst, const void* src, int sz){
  asm volatile("cp.async.cg.shared.global [%0], [%1], 16, %2;"
               :: "r"(dst), "l"(src), "r"(sz) : "memory");
}
__device__ __forceinline__ void split_hf(float v, __half& h, __half& l){
  h = __float2half_rn(v);
  l = __float2half_rn(v - __half2float(h));
}
__device__ __forceinline__ uint32_t pack2h(__half a, __half b){
  __half2 t(a,b);
  return *reinterpret_cast<uint32_t*>(&t);
}
__device__ __forceinline__ uint32_t cvt_h2(float a, float b){
  uint32_t r; asm("cvt.rn.f16x2.f32 %0, %1, %2;" : "=r"(r) : "f"(b), "f"(a)); return r;
}
// packed dual-fp32 FMA
__device__ __forceinline__ uint64_t pk2f(float lo, float hi){
  uint64_t r; asm("mov.b64 %0, {%1,%2};" : "=l"(r) : "f"(lo), "f"(hi)); return r;
}
__device__ __forceinline__ void fma2(uint64_t& d, uint64_t a, uint64_t b){
  asm("fma.rn.f32x2 %0, %1, %2, %0;" : "+l"(d) : "l"(a), "l"(b));
}
__device__ __forceinline__ void unpk2f(uint64_t v, float& lo, float& hi){
  asm("mov.b64 {%0,%1}, %2;" : "=f"(lo), "=f"(hi) : "l"(v));
}

// ================= device scratch =================
__device__ float g_c1[64*8*1800];
__device__ __half g_a1h[64*8*1800], g_a1l[64*8*1800];
__device__ __half g_col2h[11520*808], g_col2l[11520*808];
__device__ float g_c2g[11520*80];
__device__ __half g_a2h[11520*80], g_a2l[11520*80];
__device__ __half g_col3h[1152*4080], g_col3l[1152*4080];
__device__ float g_c3[1152*800];
__device__ float g_x[1152*800];
__device__ __half g_xh[1152*800], g_xl[1152*800];
__device__ float g_qkv[1152*2400];
__device__ __half g_atth[1152*800], g_attl[1152*800];
__device__ __half g_hh[1152*3200], g_hl[1152*3200];
__device__ float g_part[3*1152*800];
__device__ float g_stats[128];
// weights: single fp16
__device__ __half g_w2[80*808];
__device__ __half g_w3[800*4080];
__device__ __half g_wip[8*2400*800];
__device__ __half g_wao[8*800*800];
__device__ __half g_wl1[8*3200*800];
__device__ __half g_wl2[8*800*3200];
__device__ __half g_wout[800*800];

// ================= merged weight conversion =================
struct WConvArgs {
  const float4* s[7];
  uint4* h[7];
  int n8[7];
};
__global__ __launch_bounds__(256) void wconv_all(WConvArgs a)
{
  const int gid = blockIdx.x*256 + threadIdx.x;
  const int stride = gridDim.x*256;
  #pragma unroll 1
  for (int si = 0; si < 7; ++si) {
    const float4* __restrict__ S = a.s[si];
    uint4* __restrict__ H = a.h[si];
    const int n = a.n8[si];
    for (int i = gid; i < n; i += stride) {
      float4 x = S[2*i], y = S[2*i+1];
      H[i] = make_uint4(cvt_h2(x.x,x.y), cvt_h2(x.z,x.w),
                        cvt_h2(y.x,y.y), cvt_h2(y.z,y.w));
    }
  }
}

#define PADK 40
#define ALOFF (64u*PADK*2)
#define BOFF  (128u*PADK*2)
#define STAGE4_BYTES (256*PADK*2)   // 20480
#define GEMM4_SMEM (2*STAGE4_BYTES) // 40960

// OUTBF: 0=fp32+bias(+ACT), 1=fp16 hi/lo+bias(+ACT), 2=raw fp32 partial (split-K via gridDim.z)
template<int ACT, int OUTBF>
__global__ void __launch_bounds__(256) gemm4(
    const __half* __restrict__ Ah, const __half* __restrict__ Al,
    const __half* __restrict__ B,
    const float* __restrict__ bias, float* __restrict__ C,
    __half* __restrict__ Ch, __half* __restrict__ Cl,
    int M, int N, int K)
{
  extern __shared__ __align__(16) __half sm[];
  const int tid = threadIdx.x;
  const int wid = tid >> 5;
  const int lane = tid & 31;
  const int g = lane >> 2;
  const int t2 = (lane & 3) * 2;
  const int wm = wid >> 2;
  const int wn = wid & 3;
  const int bm = blockIdx.y * 64;
  const int bn = blockIdx.x * 128;
  const uint32_t smb = smem_u32(sm);

  const int j8 = lane >> 3, lr = lane & 7;
  const uint32_t offA0 = (uint32_t)((wm*32 + 0*16 + (j8&1)*8 + lr)*PADK + (j8>>1)*8)*2;
  const uint32_t offA1 = (uint32_t)((wm*32 + 1*16 + (j8&1)*8 + lr)*PADK + (j8>>1)*8)*2;
  const uint32_t offB0 = (uint32_t)((wn*32 + 0*16 + (j8>>1)*8 + lr)*PADK + (j8&1)*8)*2;
  const uint32_t offB1 = (uint32_t)((wn*32 + 1*16 + (j8>>1)*8 + lr)*PADK + (j8&1)*8)*2;

  float acc[2][4][4];
  #pragma unroll
  for (int i=0;i<2;++i)
    #pragma unroll
    for (int jj=0;jj<4;++jj)
      #pragma unroll
      for (int k=0;k<4;++k) acc[i][jj][k]=0.f;

  const int nst   = CDIV(K, 32);
  const int chunk = CDIV(nst, (int)gridDim.z);
  const int sbeg  = blockIdx.z * chunk;
  const int send  = min(nst, sbeg + chunk);

  auto load_stage = [&](int s){
    const uint32_t base = smb + (uint32_t)(s & 1) * STAGE4_BYTES;
    const int k0 = s * 32;
    {
      int r = tid >> 2, c = (tid & 3) * 8;
      uint32_t d = base + (uint32_t)(r*PADK + c)*2;
      int gk = k0 + c;
      int sz = (gk < K) ? 16 : 0;
      size_t off = (size_t)(bm + r)*K + (sz ? gk : 0);
      cp16(d,         Ah + off, sz);
      cp16(d + ALOFF, Al + off, sz);
    }
    #pragma unroll
    for (int jj = 0; jj < 2; ++jj) {
      int sid = tid + jj*256;
      int r = sid >> 2, c = (sid & 3) * 8;
      uint32_t d = base + BOFF + (uint32_t)(r*PADK + c)*2;
      int gk = k0 + c;
      int rb = bn + r;
      int sz = (rb < N && gk < K) ? 16 : 0;
      size_t off = (size_t)(sz ? rb : 0)*K + (sz ? gk : 0);
      cp16(d, B + off, sz);
    }
    asm volatile("cp.async.commit_group;" ::: "memory");
  };

  load_stage(sbeg);

  for (int s = sbeg; s < send; ++s) {
    if (s + 1 < send) {
      load_stage(s + 1);
      asm volatile("cp.async.wait_group 1;" ::: "memory");
    } else {
      asm volatile("cp.async.wait_group 0;" ::: "memory");
    }
    __syncthreads();

    const uint32_t stA = smb + (uint32_t)(s & 1) * STAGE4_BYTES;
    const uint32_t stB = stA + BOFF;

    #pragma unroll
    for (int ks = 0; ks < 32; ks += 16) {
      const uint32_t kd = (uint32_t)ks * 2;
      uint32_t ah0[4], ah1[4], al0[4], al1[4], bq0[4], bq1[4];
      ldm4(ah0, stA + offA0 + kd);
      ldm4(ah1, stA + offA1 + kd);
      ldm4(al0, stA + ALOFF + offA0 + kd);
      ldm4(al1, stA + ALOFF + offA1 + kd);
      ldm4(bq0, stB + offB0 + kd);
      ldm4(bq1, stB + offB1 + kd);

      const uint32_t* bf[4] = { &bq0[0], &bq0[2], &bq1[0], &bq1[2] };
      uint32_t* ah[2] = { ah0, ah1 };
      uint32_t* al[2] = { al0, al1 };

      #pragma unroll
      for (int mf = 0; mf < 2; ++mf)
        #pragma unroll
        for (int nf = 0; nf < 4; ++nf) {
          mma16816(acc[mf][nf], ah[mf], bf[nf]);
          mma16816(acc[mf][nf], al[mf], bf[nf]);
        }
    }
    __syncthreads();
  }

  float* Cz = (OUTBF == 2) ? (C + (size_t)blockIdx.z * M * N) : C;

  #pragma unroll
  for (int mf = 0; mf < 2; ++mf) {
    int row0 = bm + wm*32 + mf*16 + g;
    #pragma unroll
    for (int nf = 0; nf < 4; ++nf) {
      int col = bn + wn*32 + nf*8 + t2;
      if (col >= N) continue;
      if (OUTBF == 2) {
        if (col+1 < N) {
          *(float2*)(Cz + (size_t)row0*N + col)     = make_float2(acc[mf][nf][0], acc[mf][nf][1]);
          *(float2*)(Cz + (size_t)(row0+8)*N + col) = make_float2(acc[mf][nf][2], acc[mf][nf][3]);
        } else {
          Cz[(size_t)row0*N + col]     = acc[mf][nf][0];
          Cz[(size_t)(row0+8)*N + col] = acc[mf][nf][2];
        }
        continue;
      }
      float b0 = bias[col];
      float b1 = (col+1 < N) ? bias[col+1] : 0.f;
      float v0 = acc[mf][nf][0] + b0, v1 = acc[mf][nf][1] + b1;
      float v2 = acc[mf][nf][2] + b0, v3 = acc[mf][nf][3] + b1;
      if (ACT == 1) { v0=gelu_f(v0); v1=gelu_f(v1); v2=gelu_f(v2); v3=gelu_f(v3); }
      if (OUTBF == 0) {
        if (col+1 < N) {
          *(float2*)(Cz + (size_t)row0*N + col)     = make_float2(v0, v1);
          *(float2*)(Cz + (size_t)(row0+8)*N + col) = make_float2(v2, v3);
        } else {
          Cz[(size_t)row0*N + col] = v0;
          Cz[(size_t)(row0+8)*N + col] = v2;
        }
      } else {
        __half h0,l0,h1,l1;
        if (col+1 < N) {
          split_hf(v0,h0,l0); split_hf(v1,h1,l1);
          *(uint32_t*)(Ch + (size_t)row0*N + col) = pack2h(h0,h1);
          *(uint32_t*)(Cl + (size_t)row0*N + col) = pack2h(l0,l1);
          split_hf(v2,h0,l0); split_hf(v3,h1,l1);
          *(uint32_t*)(Ch + (size_t)(row0+8)*N + col) = pack2h(h0,h1);
          *(uint32_t*)(Cl + (size_t)(row0+8)*N + col) = pack2h(l0,l1);
        } else {
          split_hf(v0,h0,l0); Ch[(size_t)row0*N+col]=h0;     Cl[(size_t)row0*N+col]=l0;
          split_hf(v2,h0,l0); Ch[(size_t)(row0+8)*N+col]=h0; Cl[(size_t)(row0+8)*N+col]=l0;
        }
      }
    }
  }
}

// ===== split-K reduce (float4) =====
__global__ void red_plain(const float4* __restrict__ p, const float* __restrict__ bias,
                          float4* __restrict__ C, int MN4, int N, int nz)
{
  int i = blockIdx.x*256 + threadIdx.x;
  if (i >= MN4) return;
  int col = (i*4) % N;
  float4 v = *(const float4*)&bias[col];
  for (int z = 0; z < nz; ++z) {
    float4 pv = p[(size_t)z*MN4 + i];
    v.x += pv.x; v.y += pv.y; v.z += pv.z; v.w += pv.w;
  }
  C[i] = v;
}

// ===== split-K(3) reduce fused with residual add + LayerNorm (float4) =====
__global__ __launch_bounds__(256) void red_add_ln(float* __restrict__ x,
    __half* __restrict__ xh, __half* __restrict__ xl,
    const float* __restrict__ p, const float* __restrict__ bias,
    const float* __restrict__ g, const float* __restrict__ be)
{
  const int row = blockIdx.x;
  const int tid = threadIdx.x;
  const int MN4 = 1152*200;
  __shared__ float t[800];
  __shared__ float sh1[256], sh2[256];
  float s = 0.f, q = 0.f;
  if (tid < 200) {
    size_t o4 = (size_t)row*200 + tid;
    float4 xv = ((const float4*)x)[o4];
    float4 p0 = ((const float4*)p)[o4];
    float4 p1 = ((const float4*)p)[MN4 + o4];
    float4 p2 = ((const float4*)p)[2*MN4 + o4];
    float4 bv = ((const float4*)bias)[tid];
    float v0 = xv.x + p0.x + p1.x + p2.x + bv.x;
    float v1 = xv.y + p0.y + p1.y + p2.y + bv.y;
    float v2 = xv.z + p0.z + p1.z + p2.z + bv.z;
    float v3 = xv.w + p0.w + p1.w + p2.w + bv.w;
    t[tid*4+0]=v0; t[tid*4+1]=v1; t[tid*4+2]=v2; t[tid*4+3]=v3;
    s = v0+v1+v2+v3;
    q = v0*v0+v1*v1+v2*v2+v3*v3;
  }
  sh1[tid] = s; sh2[tid] = q;
  __syncthreads();
  for (int st = 128; st > 0; st >>= 1) {
    if (tid < st) { sh1[tid] += sh1[tid+st]; sh2[tid] += sh2[tid+st]; }
    __syncthreads();
  }
  float m = sh1[0] / 800.f;
  float r = rsqrtf(sh2[0] / 800.f - m*m + 1e-5f);
  if (tid < 200) {
    float4 gv = ((const float4*)g)[tid];
    float4 bev = ((const float4*)be)[tid];
    float v0 = (t[tid*4+0]-m)*r*gv.x + bev.x;
    float v1 = (t[tid*4+1]-m)*r*gv.y + bev.y;
    float v2 = (t[tid*4+2]-m)*r*gv.z + bev.z;
    float v3 = (t[tid*4+3]-m)*r*gv.w + bev.w;
    size_t o4 = (size_t)row*200 + tid;
    ((float4*)x)[o4] = make_float4(v0,v1,v2,v3);
    __half h0,l0,h1,l1,h2,l2,h3,l3;
    split_hf(v0,h0,l0); split_hf(v1,h1,l1); split_hf(v2,h2,l2); split_hf(v3,h3,l3);
    ((uint2*)xh)[o4] = make_uint2(pack2h(h0,h1), pack2h(h2,h3));
    ((uint2*)xl)[o4] = make_uint2(pack2h(l0,l1), pack2h(l2,l3));
  }
}

// ================= conv1 (round-12 exact: f32x2, grid 64x4) =================
__global__ __launch_bounds__(128) void conv1_kernel(const float* __restrict__ src,
    const float* __restrict__ w, const float* __restrict__ bias, float* __restrict__ out)
{
  const int b  = blockIdx.x;
  const int l0 = blockIdx.y * 450;
  const int t  = threadIdx.x;
  __shared__ float s_in[2464];
  __shared__ float s_wt[1632];
  uint64_t acc2[4][4];
  #pragma unroll
  for (int j=0;j<4;++j)
    #pragma unroll
    for (int p=0;p<4;++p) acc2[j][p] = pk2f(0.f, 0.f);
  const int base = 5*l0 - 100;
  const int tc = (t < 112) ? t : 112;

  for (int i = 0; i < 12; ++i) {
    __syncthreads();
    for (int j = t; j < 2464; j += 128) {
      int p = base + j;
      s_in[j] = (p >= 0 && p < 9000) ? src[(size_t)(b*12+i)*9000 + p] : 0.f;
    }
    for (int j = t; j < 1632; j += 128) {
      int o = j & 7, k = j >> 3;
      s_wt[j] = (k < 201) ? w[(size_t)(o*12 + i)*201 + k] : 0.f;
    }
    __syncthreads();

    for (int k0 = 0; k0 < 201; k0 += 4) {
      float buf[24];
      {
        const float4* p4 = (const float4*)&s_in[20*tc + k0];
        #pragma unroll
        for (int q=0;q<6;++q) {
          float4 v = p4[q];
          buf[4*q]=v.x; buf[4*q+1]=v.y; buf[4*q+2]=v.z; buf[4*q+3]=v.w;
        }
      }
      uint64_t wr2[4][4];
      #pragma unroll
      for (int kk=0;kk<4;++kk) {
        float4 a = *(const float4*)&s_wt[(k0+kk)*8];
        float4 c = *(const float4*)&s_wt[(k0+kk)*8+4];
        wr2[kk][0]=pk2f(a.x,a.y); wr2[kk][1]=pk2f(a.z,a.w);
        wr2[kk][2]=pk2f(c.x,c.y); wr2[kk][3]=pk2f(c.z,c.w);
      }
      #pragma unroll
      for (int j=0;j<4;++j)
        #pragma unroll
        for (int kk=0;kk<4;++kk) {
          float in = buf[5*j+kk];
          uint64_t in2 = pk2f(in, in);
          #pragma unroll
          for (int p=0;p<4;++p) fma2(acc2[j][p], in2, wr2[kk][p]);
        }
    }
  }

  if (t <= 112) {
    #pragma unroll
    for (int j=0;j<4;++j) {
      int lt = 4*t + j;
      if (lt < 450) {
        int l = l0 + lt;
        #pragma unroll
        for (int p=0;p<4;++p) {
          float lo, hi;
          unpk2f(acc2[j][p], lo, hi);
          out[(size_t)(b*8 + 2*p    )*1800 + l] = lo + bias[2*p];
          out[(size_t)(b*8 + 2*p + 1)*1800 + l] = hi + bias[2*p+1];
        }
      }
    }
  }
}

// ================= GroupNorm(1) stats =================
__global__ __launch_bounds__(256) void gn_stats_kernel(const float* __restrict__ x,
                                                       float* __restrict__ stats, int n)
{
  const int b = blockIdx.x;
  const float* xb = x + (size_t)b * n;
  float s = 0.f, q = 0.f;
  for (int i = threadIdx.x; i < n; i += 256) { float v = xb[i]; s += v; q += v*v; }
  __shared__ float sh1[256], sh2[256];
  sh1[threadIdx.x] = s; sh2[threadIdx.x] = q;
  __syncthreads();
  for (int st = 128; st > 0; st >>= 1) {
    if (threadIdx.x < st) { sh1[threadIdx.x] += sh1[threadIdx.x+st]; sh2[threadIdx.x] += sh2[threadIdx.x+st]; }
    __syncthreads();
  }
  if (threadIdx.x == 0) {
    float m = sh1[0] / n;
    float v = sh2[0] / n - m*m;
    stats[2*b]   = m;
    stats[2*b+1] = rsqrtf(v + 1e-5f);
  }
}

// ===== GN1 apply + GELU + split (float4) =====
__global__ void gn1_apply_split(const float* __restrict__ c1,
    __half* __restrict__ ah, __half* __restrict__ al,
    const float* __restrict__ stats, const float* __restrict__ g, const float* __restrict__ be)
{
  int i4 = blockIdx.x*256 + threadIdx.x;
  if (i4 >= 64*8*450) return;
  int idx = i4*4;
  int b = idx / 14400;
  int i = (idx / 1800) & 7;
  float m = stats[2*b], r = stats[2*b+1];
  float gg = g[i], bb = be[i];
  float4 v4 = ((const float4*)c1)[i4];
  float v0 = gelu_f((v4.x-m)*r*gg + bb);
  float v1 = gelu_f((v4.y-m)*r*gg + bb);
  float v2 = gelu_f((v4.z-m)*r*gg + bb);
  float v3 = gelu_f((v4.w-m)*r*gg + bb);
  __half h0,l0,h1,l1,h2,l2,h3,l3;
  split_hf(v0,h0,l0); split_hf(v1,h1,l1); split_hf(v2,h2,l2); split_hf(v3,h3,l3);
  ((uint2*)ah)[i4] = make_uint2(pack2h(h0,h1), pack2h(h2,h3));
  ((uint2*)al)[i4] = make_uint2(pack2h(l0,l1), pack2h(l2,l3));
}

// ===== im2col2 gather =====
__global__ __launch_bounds__(256) void im2col2_gather(
    const __half* __restrict__ ah, const __half* __restrict__ al,
    __half* __restrict__ colh, __half* __restrict__ coll)
{
  const int l = blockIdx.x;
  const int b = blockIdx.y;
  const size_t rowo = ((size_t)(b*180 + l))*808;
  const int p0 = 10*l - 50;
  for (int c = threadIdx.x; c < 808; c += 256) {
    int i = c / 101;
    int kk = c - 101*i;
    int p = p0 + kk;
    __half h = __float2half(0.f), lo = __float2half(0.f);
    if (p >= 0 && p < 1800) {
      size_t src = (size_t)(b*8+i)*1800 + p;
      h = ah[src]; lo = al[src];
    }
    colh[rowo + c] = h; coll[rowo + c] = lo;
  }
}

// ===== GN2 apply + GELU + split (float4) =====
__global__ void gn2_apply_split(const float* __restrict__ c2g,
    __half* __restrict__ ah, __half* __restrict__ al,
    const float* __restrict__ stats, const float* __restrict__ g, const float* __restrict__ be)
{
  int i4 = blockIdx.x*256 + threadIdx.x;
  if (i4 >= 11520*20) return;
  int idx = i4*4;
  int b = idx / (180*80);
  int i0 = idx % 80;
  float m = stats[2*b], r = stats[2*b+1];
  float4 gv = *(const float4*)&g[i0];
  float4 bv = *(const float4*)&be[i0];
  float4 v4 = ((const float4*)c2g)[i4];
  float v0 = gelu_f((v4.x-m)*r*gv.x + bv.x);
  float v1 = gelu_f((v4.y-m)*r*gv.y + bv.y);
  float v2 = gelu_f((v4.z-m)*r*gv.z + bv.z);
  float v3 = gelu_f((v4.w-m)*r*gv.w + bv.w);
  __half h0,l0,h1,l1,h2,l2,h3,l3;
  split_hf(v0,h0,l0); split_hf(v1,h1,l1); split_hf(v2,h2,l2); split_hf(v3,h3,l3);
  ((uint2*)ah)[i4] = make_uint2(pack2h(h0,h1), pack2h(h2,h3));
  ((uint2*)al)[i4] = make_uint2(pack2h(l0,l1), pack2h(l2,l3));
}

// ===== im2col3 gather =====
__global__ __launch_bounds__(256) void im2col3_gather(
    const __half* __restrict__ ah, const __half* __restrict__ al,
    __half* __restrict__ colh, __half* __restrict__ coll)
{
  const int l = blockIdx.x;
  const int b = blockIdx.y;
  const size_t rowo = ((size_t)(b*18 + l))*4080;
  const int p0 = 10*l - 25;
  for (int c = threadIdx.x; c < 4080; c += 256) {
    int i = c / 51;
    int k = c - 51*i;
    int p = p0 + k;
    __half h = __float2half(0.f), lo = __float2half(0.f);
    if (p >= 0 && p < 180) {
      size_t src = (size_t)(b*180+p)*80 + i;
      h = ah[src]; lo = al[src];
    }
    colh[rowo + c] = h; coll[rowo + c] = lo;
  }
}

// GN3 + GELU + PE (float4)
__global__ void gn3_pe_kernel(const float* __restrict__ x, float* __restrict__ y,
    __half* __restrict__ yh, __half* __restrict__ yl,
    const float* __restrict__ stats, const float* __restrict__ g, const float* __restrict__ be)
{
  int i4 = blockIdx.x*blockDim.x + threadIdx.x;
  if (i4 >= 1152*200) return;
  int idx = i4*4;
  int row = idx / 800, d0 = idx % 800;
  int b = row / 18, s = row % 18;
  float m = stats[2*b], r = stats[2*b+1];
  float4 gv = *(const float4*)&g[d0];
  float4 bv = *(const float4*)&be[d0];
  float4 v4 = ((const float4*)x)[i4];
  float vv[4] = {
    gelu_f((v4.x-m)*r*gv.x + bv.x),
    gelu_f((v4.y-m)*r*gv.y + bv.y),
    gelu_f((v4.z-m)*r*gv.z + bv.z),
    gelu_f((v4.w-m)*r*gv.w + bv.w)
  };
  #pragma unroll
  for (int q = 0; q < 4; ++q) {
    int d = d0 + q;
    int de = d & ~1;
    float freq = expf((float)de * (-9.210340371976184f/800.f));
    float ang = (float)s * freq;
    vv[q] += (d & 1) ? cosf(ang) : sinf(ang);
  }
  ((float4*)y)[i4] = make_float4(vv[0],vv[1],vv[2],vv[3]);
  __half h0,l0,h1,l1,h2,l2,h3,l3;
  split_hf(vv[0],h0,l0); split_hf(vv[1],h1,l1); split_hf(vv[2],h2,l2); split_hf(vv[3],h3,l3);
  ((uint2*)yh)[i4] = make_uint2(pack2h(h0,h1), pack2h(h2,h3));
  ((uint2*)yl)[i4] = make_uint2(pack2h(l0,l1), pack2h(l2,l3));
}

// ================= attention (vectorized) =================
__global__ __launch_bounds__(128) void attn_kernel(const float* __restrict__ qkv,
    __half* __restrict__ outh, __half* __restrict__ outl)
{
  const int b = blockIdx.x, h = blockIdx.y;
  const int tid = threadIdx.x;
  __shared__ float sq[1800], sk[1800], sv[1800], sc[324];
  const float4* qkv4 = (const float4*)qkv;
  for (int idx = tid; idx < 450; idx += 128) {
    int s = idx / 25, d4 = idx % 25;
    size_t base = (size_t)(b*18+s)*600 + h*25 + d4;
    *(float4*)&sq[s*100 + d4*4] = qkv4[base];
    *(float4*)&sk[s*100 + d4*4] = qkv4[base + 200];
    *(float4*)&sv[s*100 + d4*4] = qkv4[base + 400];
  }
  __syncthreads();
  for (int p = tid; p < 324; p += 128) {
    int i = p/18, j = p%18;
    float dot = 0.f;
    #pragma unroll 4
    for (int d = 0; d < 100; ++d) dot = fmaf(sq[i*100+d], sk[j*100+d], dot);
    int di = i - j; if (di < 0) di = -di;
    float bias = (di > 2 && i != 0 && j != 0) ? -1e30f : 0.f;
    sc[p] = dot * 0.1f + bias;
  }
  __syncthreads();
  if (tid < 18) {
    float mx = -1e30f;
    for (int j = 0; j < 18; ++j) mx = fmaxf(mx, sc[tid*18+j]);
    float sum = 0.f;
    for (int j = 0; j < 18; ++j) { float e = expf(sc[tid*18+j]-mx); sc[tid*18+j] = e; sum += e; }
    float inv = 1.f/sum;
    for (int j = 0; j < 18; ++j) sc[tid*18+j] *= inv;
  }
  __syncthreads();
  for (int idx = tid; idx < 450; idx += 128) {
    int i = idx / 25, d4 = idx % 25;
    float o0=0.f,o1=0.f,o2=0.f,o3=0.f;
    #pragma unroll
    for (int j = 0; j < 18; ++j) {
      float wgt = sc[i*18+j];
      float4 v = *(const float4*)&sv[j*100 + d4*4];
      o0 = fmaf(wgt, v.x, o0); o1 = fmaf(wgt, v.y, o1);
      o2 = fmaf(wgt, v.z, o2); o3 = fmaf(wgt, v.w, o3);
    }
    size_t o4 = ((size_t)(b*18+i)*800 + h*100 + d4*4) >> 2;
    __half h0,l0,h1,l1,h2,l2,h3,l3;
    split_hf(o0,h0,l0); split_hf(o1,h1,l1); split_hf(o2,h2,l2); split_hf(o3,h3,l3);
    ((uint2*)outh)[o4] = make_uint2(pack2h(h0,h1), pack2h(h2,h3));
    ((uint2*)outl)[o4] = make_uint2(pack2h(l0,l1), pack2h(l2,l3));
  }
}

// ================= host =================
static float* symf(const void* s){ void* p; cudaGetSymbolAddress(&p, s); return (float*)p; }
static __half* symh(const void* s){ void* p; cudaGetSymbolAddress(&p, s); return (__half*)p; }

extern "C" void kernel_launch(void* const* d_in, const int* in_sizes, int n_in,
                              void* d_out, int out_size)
{
  const float* src        = (const float*)d_in[0];
  const float* cw1        = (const float*)d_in[1];
  const float* cb1        = (const float*)d_in[2];
  const float* gn1_g      = (const float*)d_in[3];
  const float* gn1_b      = (const float*)d_in[4];
  const float* cw2        = (const float*)d_in[5];
  const float* cb2        = (const float*)d_in[6];
  const float* gn2_g      = (const float*)d_in[7];
  const float* gn2_b      = (const float*)d_in[8];
  const float* cw3        = (const float*)d_in[9];
  const float* cb3        = (const float*)d_in[10];
  const float* gn3_g      = (const float*)d_in[11];
  const float* gn3_b      = (const float*)d_in[12];
  const float* in_proj_w  = (const float*)d_in[13];
  const float* in_proj_b  = (const float*)d_in[14];
  const float* attn_out_w = (const float*)d_in[15];
  const float* attn_out_b = (const float*)d_in[16];
  const float* lin1_w     = (const float*)d_in[17];
  const float* lin1_b     = (const float*)d_in[18];
  const float* lin2_w     = (const float*)d_in[19];
  const float* lin2_b     = (const float*)d_in[20];
  const float* ln1_g      = (const float*)d_in[21];
  const float* ln1_b      = (const float*)d_in[22];
  const float* ln2_g      = (const float*)d_in[23];
  const float* ln2_b      = (const float*)d_in[24];
  const float* out_w      = (const float*)d_in[25];
  const float* out_b      = (const float*)d_in[26];

  float* c1   = symf(g_c1);
  float* c2g  = symf(g_c2g);
  float* c3   = symf(g_c3);
  float* x    = symf(g_x);
  float* qkv  = symf(g_qkv);
  float* part = symf(g_part);
  float* st   = symf(g_stats);
  __half *a1h=symh(g_a1h), *a1l=symh(g_a1l);
  __half *a2h=symh(g_a2h), *a2l=symh(g_a2l);
  __half *col2h=symh(g_col2h), *col2l=symh(g_col2l);
  __half *col3h=symh(g_col3h), *col3l=symh(g_col3l);
  __half *xh=symh(g_xh), *xl=symh(g_xl);
  __half *atth=symh(g_atth), *attl=symh(g_attl);
  __half *hh=symh(g_hh), *hl=symh(g_hl);
  __half *w2=symh(g_w2), *w3=symh(g_w3), *wip=symh(g_wip), *wao=symh(g_wao);
  __half *wl1=symh(g_wl1), *wl2=symh(g_wl2), *wout=symh(g_wout);

  cudaFuncSetAttribute(gemm4<0,0>, cudaFuncAttributeMaxDynamicSharedMemorySize, GEMM4_SMEM);
  cudaFuncSetAttribute(gemm4<1,1>, cudaFuncAttributeMaxDynamicSharedMemorySize, GEMM4_SMEM);
  cudaFuncSetAttribute(gemm4<0,2>, cudaFuncAttributeMaxDynamicSharedMemorySize, GEMM4_SMEM);

  // ---- merged weight conversion ----
  {
    WConvArgs a;
    a.s[0]=(const float4*)cw2;        a.h[0]=(uint4*)w2;   a.n8[0]=80*808/8;
    a.s[1]=(const float4*)cw3;        a.h[1]=(uint4*)w3;   a.n8[1]=800*4080/8;
    a.s[2]=(const float4*)in_proj_w;  a.h[2]=(uint4*)wip;  a.n8[2]=8*2400*800/8;
    a.s[3]=(const float4*)attn_out_w; a.h[3]=(uint4*)wao;  a.n8[3]=8*800*800/8;
    a.s[4]=(const float4*)lin1_w;     a.h[4]=(uint4*)wl1;  a.n8[4]=8*3200*800/8;
    a.s[5]=(const float4*)lin2_w;     a.h[5]=(uint4*)wl2;  a.n8[5]=8*800*3200/8;
    a.s[6]=(const float4*)out_w;      a.h[6]=(uint4*)wout; a.n8[6]=800*800/8;
    wconv_all<<<1184,256>>>(a);
  }

  // ---- patch embedding ----
  conv1_kernel<<<dim3(64,4),128>>>(src, cw1, cb1, c1);
  gn_stats_kernel<<<64,256>>>(c1, st, 8*1800);
  gn1_apply_split<<<CDIV(64*8*450,256),256>>>(c1, a1h, a1l, st, gn1_g, gn1_b);
  im2col2_gather<<<dim3(180,64),256>>>(a1h, a1l, col2h, col2l);
  gemm4<0,2><<<dim3(1,180,2),256,GEMM4_SMEM>>>(col2h, col2l, w2, nullptr, part,
                                               nullptr, nullptr, 11520, 80, 808);
  red_plain<<<CDIV(11520*20,256),256>>>((const float4*)part, cb2, (float4*)c2g, 11520*20, 80, 2);
  gn_stats_kernel<<<64,256>>>(c2g, st, 180*80);
  gn2_apply_split<<<CDIV(11520*20,256),256>>>(c2g, a2h, a2l, st, gn2_g, gn2_b);
  im2col3_gather<<<dim3(18,64),256>>>(a2h, a2l, col3h, col3l);
  gemm4<0,2><<<dim3(7,18,3),256,GEMM4_SMEM>>>(col3h, col3l, w3, nullptr, part,
                                              nullptr, nullptr, 1152, 800, 4080);
  red_plain<<<CDIV(1152*200,256),256>>>((const float4*)part, cb3, (float4*)c3, 1152*200, 800, 3);
  gn_stats_kernel<<<64,256>>>(c3, st, 18*800);
  gn3_pe_kernel<<<CDIV(1152*200,256),256>>>(c3, x, xh, xl, st, gn3_g, gn3_b);

  // ---- transformer layers (split-K=3 on N=800 GEMMs) ----
  for (int i = 0; i < 8; ++i) {
    gemm4<0,0><<<dim3(19,18),256,GEMM4_SMEM>>>(xh, xl,
        wip + (size_t)i*2400*800,
        in_proj_b + (size_t)i*2400, qkv, nullptr, nullptr, 1152, 2400, 800);
    attn_kernel<<<dim3(64,8),128>>>(qkv, atth, attl);
    gemm4<0,2><<<dim3(7,18,3),256,GEMM4_SMEM>>>(atth, attl,
        wao + (size_t)i*800*800,
        nullptr, part, nullptr, nullptr, 1152, 800, 800);
    red_add_ln<<<1152,256>>>(x, xh, xl, part, attn_out_b + (size_t)i*800,
                             ln1_g + (size_t)i*800, ln1_b + (size_t)i*800);
    gemm4<1,1><<<dim3(25,18),256,GEMM4_SMEM>>>(xh, xl,
        wl1 + (size_t)i*3200*800,
        lin1_b + (size_t)i*3200, nullptr, hh, hl, 1152, 3200, 800);
    gemm4<0,2><<<dim3(7,18,3),256,GEMM4_SMEM>>>(hh, hl,
        wl2 + (size_t)i*800*3200,
        nullptr, part, nullptr, nullptr, 1152, 800, 3200);
    red_add_ln<<<1152,256>>>(x, xh, xl, part, lin2_b + (size_t)i*800,
                             ln2_g + (size_t)i*800, ln2_b + (size_t)i*800);
  }

  // ---- output projection (split-K=3 + reduce into d_out) ----
  gemm4<0,2><<<dim3(7,18,3),256,GEMM4_SMEM>>>(xh, xl, wout, nullptr, part,
                                              nullptr, nullptr, 1152, 800, 800);
  red_plain<<<CDIV(1152*200,256),256>>>((const float4*)part, out_b, (float4*)d_out, 1152*200, 800, 3);
}

// round 17
// speedup vs baseline: 1.1491x; 1.0112x over previous
#include <cuda_runtime.h>
#include <cuda_fp16.h>
#include <math.h>
#include <stdint.h>

#define CDIV(a,b) (((a)+(b)-1)/(b))

__device__ __forceinline__ float gelu_f(float x){
  const float c0 = 0.7978845608028654f;
  return 0.5f*x*(1.f + tanhf(c0*(x + 0.044715f*x*x*x)));
}
__device__ __forceinline__ void mma16816(float* d, const uint32_t* a, const uint32_t* b){
  asm volatile(
    "mma.sync.aligned.m16n8k16.row.col.f32.f16.f16.f32 "
    "{%0,%1,%2,%3}, {%4,%5,%6,%7}, {%8,%9}, {%0,%1,%2,%3};"
    : "+f"(d[0]), "+f"(d[1]), "+f"(d[2]), "+f"(d[3])
    : "r"(a[0]), "r"(a[1]), "r"(a[2]), "r"(a[3]), "r"(b[0]), "r"(b[1]));
}
__device__ __forceinline__ void ldm4(uint32_t* r, uint32_t addr){
  asm volatile("ldmatrix.sync.aligned.m8n8.x4.shared.b16 {%0,%1,%2,%3}, [%4];"
    : "=r"(r[0]), "=r"(r[1]), "=r"(r[2]), "=r"(r[3]) : "r"(addr));
}
__device__ __forceinline__ uint32_t smem_u32(const void* p){
  uint32_t a;
  asm("{ .reg .u64 t; cvta.to.shared.u64 t, %1; cvt.u32.u64 %0, t; }" : "=r"(a) : "l"(p));
  return a;
}
__device__ __forceinline__ void cp16(uint32_t dst, const void* src, int sz){
  asm volatile("cp.async.cg.shared.global [%0], [%1], 16, %2;"
               :: "r"(dst), "l"(src), "r"(sz) : "memory");
}
__device__ __forceinline__ void split_hf(float v, __half& h, __half& l){
  h = __float2half_rn(v);
  l = __float2half_rn(v - __half2float(h));
}
__device__ __forceinline__ uint32_t pack2h(__half a, __half b){
  __half2 t(a,b);
  return *reinterpret_cast<uint32_t*>(&t);
}
__device__ __forceinline__ uint32_t cvt_h2(float a, float b){
  uint32_t r; asm("cvt.rn.f16x2.f32 %0, %1, %2;" : "=r"(r) : "f"(b), "f"(a)); return r;
}
// packed dual-fp32 FMA
__device__ __forceinline__ uint64_t pk2f(float lo, float hi){
  uint64_t r; asm("mov.b64 %0, {%1,%2};" : "=l"(r) : "f"(lo), "f"(hi)); return r;
}
__device__ __forceinline__ void fma2(uint64_t& d, uint64_t a, uint64_t b){
  asm("fma.rn.f32x2 %0, %1, %2, %0;" : "+l"(d) : "l"(a), "l"(b));
}
__device__ __forceinline__ void unpk2f(uint64_t v, float& lo, float& hi){
  asm("mov.b64 {%0,%1}, %2;" : "=f"(lo), "=f"(hi) : "l"(v));
}

// ================= device scratch =================
__device__ float g_c1[64*8*1800];
__device__ __half g_a1h[64*8*1800], g_a1l[64*8*1800];
__device__ __half g_col2h[11520*808], g_col2l[11520*808];
__device__ float g_c2g[11520*80];
__device__ __half g_a2h[11520*80], g_a2l[11520*80];
__device__ __half g_col3h[1152*4080], g_col3l[1152*4080];
__device__ float g_c3[1152*800];
__device__ float g_x[1152*800];
__device__ __half g_xh[1152*800], g_xl[1152*800];
__device__ float g_qkv[1152*2400];
__device__ __half g_atth[1152*800], g_attl[1152*800];
__device__ __half g_hh[1152*3200], g_hl[1152*3200];
__device__ float g_part[3*1152*800];
__device__ float g_stats[128];
// weights: single fp16
__device__ __half g_w2[80*808];
__device__ __half g_w3[800*4080];
__device__ __half g_wip[8*2400*800];
__device__ __half g_wao[8*800*800];
__device__ __half g_wl1[8*3200*800];
__device__ __half g_wl2[8*800*3200];
__device__ __half g_wout[800*800];

// ================= merged weight conversion =================
struct WConvArgs {
  const float4* s[7];
  uint4* h[7];
  int n8[7];
};
__global__ __launch_bounds__(256) void wconv_all(WConvArgs a)
{
  const int gid = blockIdx.x*256 + threadIdx.x;
  const int stride = gridDim.x*256;
  #pragma unroll 1
  for (int si = 0; si < 7; ++si) {
    const float4* __restrict__ S = a.s[si];
    uint4* __restrict__ H = a.h[si];
    const int n = a.n8[si];
    for (int i = gid; i < n; i += stride) {
      float4 x = S[2*i], y = S[2*i+1];
      H[i] = make_uint4(cvt_h2(x.x,x.y), cvt_h2(x.z,x.w),
                        cvt_h2(y.x,y.y), cvt_h2(y.z,y.w));
    }
  }
}

#define PADK 40
#define ALOFF (64u*PADK*2)
#define BOFF  (128u*PADK*2)
#define STAGE4_BYTES (256*PADK*2)   // 20480
#define GEMM4_SMEM (2*STAGE4_BYTES) // 40960

// OUTBF: 0=fp32+bias(+ACT), 1=fp16 hi/lo+bias(+ACT), 2=raw fp32 partial (split-K via gridDim.z)
template<int ACT, int OUTBF>
__global__ void __launch_bounds__(256, 3) gemm4(
    const __half* __restrict__ Ah, const __half* __restrict__ Al,
    const __half* __restrict__ B,
    const float* __restrict__ bias, float* __restrict__ C,
    __half* __restrict__ Ch, __half* __restrict__ Cl,
    int M, int N, int K)
{
  extern __shared__ __align__(16) __half sm[];
  const int tid = threadIdx.x;
  const int wid = tid >> 5;
  const int lane = tid & 31;
  const int g = lane >> 2;
  const int t2 = (lane & 3) * 2;
  const int wm = wid >> 2;
  const int wn = wid & 3;
  const int bm = blockIdx.y * 64;
  const int bn = blockIdx.x * 128;
  const uint32_t smb = smem_u32(sm);

  const int j8 = lane >> 3, lr = lane & 7;
  const uint32_t offA0 = (uint32_t)((wm*32 + 0*16 + (j8&1)*8 + lr)*PADK + (j8>>1)*8)*2;
  const uint32_t offA1 = (uint32_t)((wm*32 + 1*16 + (j8&1)*8 + lr)*PADK + (j8>>1)*8)*2;
  const uint32_t offB0 = (uint32_t)((wn*32 + 0*16 + (j8>>1)*8 + lr)*PADK + (j8&1)*8)*2;
  const uint32_t offB1 = (uint32_t)((wn*32 + 1*16 + (j8>>1)*8 + lr)*PADK + (j8&1)*8)*2;

  float acc[2][4][4];
  #pragma unroll
  for (int i=0;i<2;++i)
    #pragma unroll
    for (int jj=0;jj<4;++jj)
      #pragma unroll
      for (int k=0;k<4;++k) acc[i][jj][k]=0.f;

  const int nst   = CDIV(K, 32);
  const int chunk = CDIV(nst, (int)gridDim.z);
  const int sbeg  = blockIdx.z * chunk;
  const int send  = min(nst, sbeg + chunk);

  auto load_stage = [&](int s){
    const uint32_t base = smb + (uint32_t)(s & 1) * STAGE4_BYTES;
    const int k0 = s * 32;
    {
      int r = tid >> 2, c = (tid & 3) * 8;
      uint32_t d = base + (uint32_t)(r*PADK + c)*2;
      int gk = k0 + c;
      int sz = (gk < K) ? 16 : 0;
      size_t off = (size_t)(bm + r)*K + (sz ? gk : 0);
      cp16(d,         Ah + off, sz);
      cp16(d + ALOFF, Al + off, sz);
    }
    #pragma unroll
    for (int jj = 0; jj < 2; ++jj) {
      int sid = tid + jj*256;
      int r = sid >> 2, c = (sid & 3) * 8;
      uint32_t d = base + BOFF + (uint32_t)(r*PADK + c)*2;
      int gk = k0 + c;
      int rb = bn + r;
      int sz = (rb < N && gk < K) ? 16 : 0;
      size_t off = (size_t)(sz ? rb : 0)*K + (sz ? gk : 0);
      cp16(d, B + off, sz);
    }
    asm volatile("cp.async.commit_group;" ::: "memory");
  };

  load_stage(sbeg);

  for (int s = sbeg; s < send; ++s) {
    if (s + 1 < send) {
      load_stage(s + 1);
      asm volatile("cp.async.wait_group 1;" ::: "memory");
    } else {
      asm volatile("cp.async.wait_group 0;" ::: "memory");
    }
    __syncthreads();

    const uint32_t stA = smb + (uint32_t)(s & 1) * STAGE4_BYTES;
    const uint32_t stB = stA + BOFF;

    #pragma unroll
    for (int ks = 0; ks < 32; ks += 16) {
      const uint32_t kd = (uint32_t)ks * 2;
      uint32_t ah0[4], ah1[4], al0[4], al1[4], bq0[4], bq1[4];
      ldm4(ah0, stA + offA0 + kd);
      ldm4(ah1, stA + offA1 + kd);
      ldm4(al0, stA + ALOFF + offA0 + kd);
      ldm4(al1, stA + ALOFF + offA1 + kd);
      ldm4(bq0, stB + offB0 + kd);
      ldm4(bq1, stB + offB1 + kd);

      const uint32_t* bf[4] = { &bq0[0], &bq0[2], &bq1[0], &bq1[2] };
      uint32_t* ah[2] = { ah0, ah1 };
      uint32_t* al[2] = { al0, al1 };

      #pragma unroll
      for (int mf = 0; mf < 2; ++mf)
        #pragma unroll
        for (int nf = 0; nf < 4; ++nf) {
          mma16816(acc[mf][nf], ah[mf], bf[nf]);
          mma16816(acc[mf][nf], al[mf], bf[nf]);
        }
    }
    __syncthreads();
  }

  float* Cz = (OUTBF == 2) ? (C + (size_t)blockIdx.z * M * N) : C;

  #pragma unroll
  for (int mf = 0; mf < 2; ++mf) {
    int row0 = bm + wm*32 + mf*16 + g;
    #pragma unroll
    for (int nf = 0; nf < 4; ++nf) {
      int col = bn + wn*32 + nf*8 + t2;
      if (col >= N) continue;
      if (OUTBF == 2) {
        if (col+1 < N) {
          *(float2*)(Cz + (size_t)row0*N + col)     = make_float2(acc[mf][nf][0], acc[mf][nf][1]);
          *(float2*)(Cz + (size_t)(row0+8)*N + col) = make_float2(acc[mf][nf][2], acc[mf][nf][3]);
        } else {
          Cz[(size_t)row0*N + col]     = acc[mf][nf][0];
          Cz[(size_t)(row0+8)*N + col] = acc[mf][nf][2];
        }
        continue;
      }
      float b0 = bias[col];
      float b1 = (col+1 < N) ? bias[col+1] : 0.f;
      float v0 = acc[mf][nf][0] + b0, v1 = acc[mf][nf][1] + b1;
      float v2 = acc[mf][nf][2] + b0, v3 = acc[mf][nf][3] + b1;
      if (ACT == 1) { v0=gelu_f(v0); v1=gelu_f(v1); v2=gelu_f(v2); v3=gelu_f(v3); }
      if (OUTBF == 0) {
        if (col+1 < N) {
          *(float2*)(Cz + (size_t)row0*N + col)     = make_float2(v0, v1);
          *(float2*)(Cz + (size_t)(row0+8)*N + col) = make_float2(v2, v3);
        } else {
          Cz[(size_t)row0*N + col] = v0;
          Cz[(size_t)(row0+8)*N + col] = v2;
        }
      } else {
        __half h0,l0,h1,l1;
        if (col+1 < N) {
          split_hf(v0,h0,l0); split_hf(v1,h1,l1);
          *(uint32_t*)(Ch + (size_t)row0*N + col) = pack2h(h0,h1);
          *(uint32_t*)(Cl + (size_t)row0*N + col) = pack2h(l0,l1);
          split_hf(v2,h0,l0); split_hf(v3,h1,l1);
          *(uint32_t*)(Ch + (size_t)(row0+8)*N + col) = pack2h(h0,h1);
          *(uint32_t*)(Cl + (size_t)(row0+8)*N + col) = pack2h(l0,l1);
        } else {
          split_hf(v0,h0,l0); Ch[(size_t)row0*N+col]=h0;     Cl[(size_t)row0*N+col]=l0;
          split_hf(v2,h0,l0); Ch[(size_t)(row0+8)*N+col]=h0; Cl[(size_t)(row0+8)*N+col]=l0;
        }
      }
    }
  }
}

// ===== split-K reduce (float4) =====
__global__ void red_plain(const float4* __restrict__ p, const float* __restrict__ bias,
                          float4* __restrict__ C, int MN4, int N, int nz)
{
  int i = blockIdx.x*256 + threadIdx.x;
  if (i >= MN4) return;
  int col = (i*4) % N;
  float4 v = *(const float4*)&bias[col];
  for (int z = 0; z < nz; ++z) {
    float4 pv = p[(size_t)z*MN4 + i];
    v.x += pv.x; v.y += pv.y; v.z += pv.z; v.w += pv.w;
  }
  C[i] = v;
}

// ===== split-K(3) reduce fused with residual add + LayerNorm (float4) =====
__global__ __launch_bounds__(256) void red_add_ln(float* __restrict__ x,
    __half* __restrict__ xh, __half* __restrict__ xl,
    const float* __restrict__ p, const float* __restrict__ bias,
    const float* __restrict__ g, const float* __restrict__ be)
{
  const int row = blockIdx.x;
  const int tid = threadIdx.x;
  const int MN4 = 1152*200;
  __shared__ float t[800];
  __shared__ float sh1[256], sh2[256];
  float s = 0.f, q = 0.f;
  if (tid < 200) {
    size_t o4 = (size_t)row*200 + tid;
    float4 xv = ((const float4*)x)[o4];
    float4 p0 = ((const float4*)p)[o4];
    float4 p1 = ((const float4*)p)[MN4 + o4];
    float4 p2 = ((const float4*)p)[2*MN4 + o4];
    float4 bv = ((const float4*)bias)[tid];
    float v0 = xv.x + p0.x + p1.x + p2.x + bv.x;
    float v1 = xv.y + p0.y + p1.y + p2.y + bv.y;
    float v2 = xv.z + p0.z + p1.z + p2.z + bv.z;
    float v3 = xv.w + p0.w + p1.w + p2.w + bv.w;
    t[tid*4+0]=v0; t[tid*4+1]=v1; t[tid*4+2]=v2; t[tid*4+3]=v3;
    s = v0+v1+v2+v3;
    q = v0*v0+v1*v1+v2*v2+v3*v3;
  }
  sh1[tid] = s; sh2[tid] = q;
  __syncthreads();
  for (int st = 128; st > 0; st >>= 1) {
    if (tid < st) { sh1[tid] += sh1[tid+st]; sh2[tid] += sh2[tid+st]; }
    __syncthreads();
  }
  float m = sh1[0] / 800.f;
  float r = rsqrtf(sh2[0] / 800.f - m*m + 1e-5f);
  if (tid < 200) {
    float4 gv = ((const float4*)g)[tid];
    float4 bev = ((const float4*)be)[tid];
    float v0 = (t[tid*4+0]-m)*r*gv.x + bev.x;
    float v1 = (t[tid*4+1]-m)*r*gv.y + bev.y;
    float v2 = (t[tid*4+2]-m)*r*gv.z + bev.z;
    float v3 = (t[tid*4+3]-m)*r*gv.w + bev.w;
    size_t o4 = (size_t)row*200 + tid;
    ((float4*)x)[o4] = make_float4(v0,v1,v2,v3);
    __half h0,l0,h1,l1,h2,l2,h3,l3;
    split_hf(v0,h0,l0); split_hf(v1,h1,l1); split_hf(v2,h2,l2); split_hf(v3,h3,l3);
    ((uint2*)xh)[o4] = make_uint2(pack2h(h0,h1), pack2h(h2,h3));
    ((uint2*)xl)[o4] = make_uint2(pack2h(l0,l1), pack2h(l2,l3));
  }
}

// ================= conv1 (round-12 exact: f32x2, grid 64x4) =================
__global__ __launch_bounds__(128) void conv1_kernel(const float* __restrict__ src,
    const float* __restrict__ w, const float* __restrict__ bias, float* __restrict__ out)
{
  const int b  = blockIdx.x;
  const int l0 = blockIdx.y * 450;
  const int t  = threadIdx.x;
  __shared__ float s_in[2464];
  __shared__ float s_wt[1632];
  uint64_t acc2[4][4];
  #pragma unroll
  for (int j=0;j<4;++j)
    #pragma unroll
    for (int p=0;p<4;++p) acc2[j][p] = pk2f(0.f, 0.f);
  const int base = 5*l0 - 100;
  const int tc = (t < 112) ? t : 112;

  for (int i = 0; i < 12; ++i) {
    __syncthreads();
    for (int j = t; j < 2464; j += 128) {
      int p = base + j;
      s_in[j] = (p >= 0 && p < 9000) ? src[(size_t)(b*12+i)*9000 + p] : 0.f;
    }
    for (int j = t; j < 1632; j += 128) {
      int o = j & 7, k = j >> 3;
      s_wt[j] = (k < 201) ? w[(size_t)(o*12 + i)*201 + k] : 0.f;
    }
    __syncthreads();

    for (int k0 = 0; k0 < 201; k0 += 4) {
      float buf[24];
      {
        const float4* p4 = (const float4*)&s_in[20*tc + k0];
        #pragma unroll
        for (int q=0;q<6;++q) {
          float4 v = p4[q];
          buf[4*q]=v.x; buf[4*q+1]=v.y; buf[4*q+2]=v.z; buf[4*q+3]=v.w;
        }
      }
      uint64_t wr2[4][4];
      #pragma unroll
      for (int kk=0;kk<4;++kk) {
        float4 a = *(const float4*)&s_wt[(k0+kk)*8];
        float4 c = *(const float4*)&s_wt[(k0+kk)*8+4];
        wr2[kk][0]=pk2f(a.x,a.y); wr2[kk][1]=pk2f(a.z,a.w);
        wr2[kk][2]=pk2f(c.x,c.y); wr2[kk][3]=pk2f(c.z,c.w);
      }
      #pragma unroll
      for (int j=0;j<4;++j)
        #pragma unroll
        for (int kk=0;kk<4;++kk) {
          float in = buf[5*j+kk];
          uint64_t in2 = pk2f(in, in);
          #pragma unroll
          for (int p=0;p<4;++p) fma2(acc2[j][p], in2, wr2[kk][p]);
        }
    }
  }

  if (t <= 112) {
    #pragma unroll
    for (int j=0;j<4;++j) {
      int lt = 4*t + j;
      if (lt < 450) {
        int l = l0 + lt;
        #pragma unroll
        for (int p=0;p<4;++p) {
          float lo, hi;
          unpk2f(acc2[j][p], lo, hi);
          out[(size_t)(b*8 + 2*p    )*1800 + l] = lo + bias[2*p];
          out[(size_t)(b*8 + 2*p + 1)*1800 + l] = hi + bias[2*p+1];
        }
      }
    }
  }
}

// ================= GroupNorm(1) stats =================
__global__ __launch_bounds__(256) void gn_stats_kernel(const float* __restrict__ x,
                                                       float* __restrict__ stats, int n)
{
  const int b = blockIdx.x;
  const float* xb = x + (size_t)b * n;
  float s = 0.f, q = 0.f;
  for (int i = threadIdx.x; i < n; i += 256) { float v = xb[i]; s += v; q += v*v; }
  __shared__ float sh1[256], sh2[256];
  sh1[threadIdx.x] = s; sh2[threadIdx.x] = q;
  __syncthreads();
  for (int st = 128; st > 0; st >>= 1) {
    if (threadIdx.x < st) { sh1[threadIdx.x] += sh1[threadIdx.x+st]; sh2[threadIdx.x] += sh2[threadIdx.x+st]; }
    __syncthreads();
  }
  if (threadIdx.x == 0) {
    float m = sh1[0] / n;
    float v = sh2[0] / n - m*m;
    stats[2*b]   = m;
    stats[2*b+1] = rsqrtf(v + 1e-5f);
  }
}

// ===== GN1 apply + GELU + split (float4) =====
__global__ void gn1_apply_split(const float* __restrict__ c1,
    __half* __restrict__ ah, __half* __restrict__ al,
    const float* __restrict__ stats, const float* __restrict__ g, const float* __restrict__ be)
{
  int i4 = blockIdx.x*256 + threadIdx.x;
  if (i4 >= 64*8*450) return;
  int idx = i4*4;
  int b = idx / 14400;
  int i = (idx / 1800) & 7;
  float m = stats[2*b], r = stats[2*b+1];
  float gg = g[i], bb = be[i];
  float4 v4 = ((const float4*)c1)[i4];
  float v0 = gelu_f((v4.x-m)*r*gg + bb);
  float v1 = gelu_f((v4.y-m)*r*gg + bb);
  float v2 = gelu_f((v4.z-m)*r*gg + bb);
  float v3 = gelu_f((v4.w-m)*r*gg + bb);
  __half h0,l0,h1,l1,h2,l2,h3,l3;
  split_hf(v0,h0,l0); split_hf(v1,h1,l1); split_hf(v2,h2,l2); split_hf(v3,h3,l3);
  ((uint2*)ah)[i4] = make_uint2(pack2h(h0,h1), pack2h(h2,h3));
  ((uint2*)al)[i4] = make_uint2(pack2h(l0,l1), pack2h(l2,l3));
}

// ===== im2col2 gather =====
__global__ __launch_bounds__(256) void im2col2_gather(
    const __half* __restrict__ ah, const __half* __restrict__ al,
    __half* __restrict__ colh, __half* __restrict__ coll)
{
  const int l = blockIdx.x;
  const int b = blockIdx.y;
  const size_t rowo = ((size_t)(b*180 + l))*808;
  const int p0 = 10*l - 50;
  for (int c = threadIdx.x; c < 808; c += 256) {
    int i = c / 101;
    int kk = c - 101*i;
    int p = p0 + kk;
    __half h = __float2half(0.f), lo = __float2half(0.f);
    if (p >= 0 && p < 1800) {
      size_t src = (size_t)(b*8+i)*1800 + p;
      h = ah[src]; lo = al[src];
    }
    colh[rowo + c] = h; coll[rowo + c] = lo;
  }
}

// ===== GN2 apply + GELU + split (float4) =====
__global__ void gn2_apply_split(const float* __restrict__ c2g,
    __half* __restrict__ ah, __half* __restrict__ al,
    const float* __restrict__ stats, const float* __restrict__ g, const float* __restrict__ be)
{
  int i4 = blockIdx.x*256 + threadIdx.x;
  if (i4 >= 11520*20) return;
  int idx = i4*4;
  int b = idx / (180*80);
  int i0 = idx % 80;
  float m = stats[2*b], r = stats[2*b+1];
  float4 gv = *(const float4*)&g[i0];
  float4 bv = *(const float4*)&be[i0];
  float4 v4 = ((const float4*)c2g)[i4];
  float v0 = gelu_f((v4.x-m)*r*gv.x + bv.x);
  float v1 = gelu_f((v4.y-m)*r*gv.y + bv.y);
  float v2 = gelu_f((v4.z-m)*r*gv.z + bv.z);
  float v3 = gelu_f((v4.w-m)*r*gv.w + bv.w);
  __half h0,l0,h1,l1,h2,l2,h3,l3;
  split_hf(v0,h0,l0); split_hf(v1,h1,l1); split_hf(v2,h2,l2); split_hf(v3,h3,l3);
  ((uint2*)ah)[i4] = make_uint2(pack2h(h0,h1), pack2h(h2,h3));
  ((uint2*)al)[i4] = make_uint2(pack2h(l0,l1), pack2h(l2,l3));
}

// ===== im2col3 gather =====
__global__ __launch_bounds__(256) void im2col3_gather(
    const __half* __restrict__ ah, const __half* __restrict__ al,
    __half* __restrict__ colh, __half* __restrict__ coll)
{
  const int l = blockIdx.x;
  const int b = blockIdx.y;
  const size_t rowo = ((size_t)(b*18 + l))*4080;
  const int p0 = 10*l - 25;
  for (int c = threadIdx.x; c < 4080; c += 256) {
    int i = c / 51;
    int k = c - 51*i;
    int p = p0 + k;
    __half h = __float2half(0.f), lo = __float2half(0.f);
    if (p >= 0 && p < 180) {
      size_t src = (size_t)(b*180+p)*80 + i;
      h = ah[src]; lo = al[src];
    }
    colh[rowo + c] = h; coll[rowo + c] = lo;
  }
}

// GN3 + GELU + PE (float4)
__global__ void gn3_pe_kernel(const float* __restrict__ x, float* __restrict__ y,
    __half* __restrict__ yh, __half* __restrict__ yl,
    const float* __restrict__ stats, const float* __restrict__ g, const float* __restrict__ be)
{
  int i4 = blockIdx.x*blockDim.x + threadIdx.x;
  if (i4 >= 1152*200) return;
  int idx = i4*4;
  int row = idx / 800, d0 = idx % 800;
  int b = row / 18, s = row % 18;
  float m = stats[2*b], r = stats[2*b+1];
  float4 gv = *(const float4*)&g[d0];
  float4 bv = *(const float4*)&be[d0];
  float4 v4 = ((const float4*)x)[i4];
  float vv[4] = {
    gelu_f((v4.x-m)*r*gv.x + bv.x),
    gelu_f((v4.y-m)*r*gv.y + bv.y),
    gelu_f((v4.z-m)*r*gv.z + bv.z),
    gelu_f((v4.w-m)*r*gv.w + bv.w)
  };
  #pragma unroll
  for (int q = 0; q < 4; ++q) {
    int d = d0 + q;
    int de = d & ~1;
    float freq = expf((float)de * (-9.210340371976184f/800.f));
    float ang = (float)s * freq;
    vv[q] += (d & 1) ? cosf(ang) : sinf(ang);
  }
  ((float4*)y)[i4] = make_float4(vv[0],vv[1],vv[2],vv[3]);
  __half h0,l0,h1,l1,h2,l2,h3,l3;
  split_hf(vv[0],h0,l0); split_hf(vv[1],h1,l1); split_hf(vv[2],h2,l2); split_hf(vv[3],h3,l3);
  ((uint2*)yh)[i4] = make_uint2(pack2h(h0,h1), pack2h(h2,h3));
  ((uint2*)yl)[i4] = make_uint2(pack2h(l0,l1), pack2h(l2,l3));
}

// ================= attention (vectorized) =================
__global__ __launch_bounds__(128) void attn_kernel(const float* __restrict__ qkv,
    __half* __restrict__ outh, __half* __restrict__ outl)
{
  const int b = blockIdx.x, h = blockIdx.y;
  const int tid = threadIdx.x;
  __shared__ float sq[1800], sk[1800], sv[1800], sc[324];
  const float4* qkv4 = (const float4*)qkv;
  for (int idx = tid; idx < 450; idx += 128) {
    int s = idx / 25, d4 = idx % 25;
    size_t base = (size_t)(b*18+s)*600 + h*25 + d4;
    *(float4*)&sq[s*100 + d4*4] = qkv4[base];
    *(float4*)&sk[s*100 + d4*4] = qkv4[base + 200];
    *(float4*)&sv[s*100 + d4*4] = qkv4[base + 400];
  }
  __syncthreads();
  for (int p = tid; p < 324; p += 128) {
    int i = p/18, j = p%18;
    float dot = 0.f;
    #pragma unroll 4
    for (int d = 0; d < 100; ++d) dot = fmaf(sq[i*100+d], sk[j*100+d], dot);
    int di = i - j; if (di < 0) di = -di;
    float bias = (di > 2 && i != 0 && j != 0) ? -1e30f : 0.f;
    sc[p] = dot * 0.1f + bias;
  }
  __syncthreads();
  if (tid < 18) {
    float mx = -1e30f;
    for (int j = 0; j < 18; ++j) mx = fmaxf(mx, sc[tid*18+j]);
    float sum = 0.f;
    for (int j = 0; j < 18; ++j) { float e = expf(sc[tid*18+j]-mx); sc[tid*18+j] = e; sum += e; }
    float inv = 1.f/sum;
    for (int j = 0; j < 18; ++j) sc[tid*18+j] *= inv;
  }
  __syncthreads();
  for (int idx = tid; idx < 450; idx += 128) {
    int i = idx / 25, d4 = idx % 25;
    float o0=0.f,o1=0.f,o2=0.f,o3=0.f;
    #pragma unroll
    for (int j = 0; j < 18; ++j) {
      float wgt = sc[i*18+j];
      float4 v = *(const float4*)&sv[j*100 + d4*4];
      o0 = fmaf(wgt, v.x, o0); o1 = fmaf(wgt, v.y, o1);
      o2 = fmaf(wgt, v.z, o2); o3 = fmaf(wgt, v.w, o3);
    }
    size_t o4 = ((size_t)(b*18+i)*800 + h*100 + d4*4) >> 2;
    __half h0,l0,h1,l1,h2,l2,h3,l3;
    split_hf(o0,h0,l0); split_hf(o1,h1,l1); split_hf(o2,h2,l2); split_hf(o3,h3,l3);
    ((uint2*)outh)[o4] = make_uint2(pack2h(h0,h1), pack2h(h2,h3));
    ((uint2*)outl)[o4] = make_uint2(pack2h(l0,l1), pack2h(l2,l3));
  }
}

// ================= host =================
static float* symf(const void* s){ void* p; cudaGetSymbolAddress(&p, s); return (float*)p; }
static __half* symh(const void* s){ void* p; cudaGetSymbolAddress(&p, s); return (__half*)p; }

extern "C" void kernel_launch(void* const* d_in, const int* in_sizes, int n_in,
                              void* d_out, int out_size)
{
  const float* src        = (const float*)d_in[0];
  const float* cw1        = (const float*)d_in[1];
  const float* cb1        = (const float*)d_in[2];
  const float* gn1_g      = (const float*)d_in[3];
  const float* gn1_b      = (const float*)d_in[4];
  const float* cw2        = (const float*)d_in[5];
  const float* cb2        = (const float*)d_in[6];
  const float* gn2_g      = (const float*)d_in[7];
  const float* gn2_b      = (const float*)d_in[8];
  const float* cw3        = (const float*)d_in[9];
  const float* cb3        = (const float*)d_in[10];
  const float* gn3_g      = (const float*)d_in[11];
  const float* gn3_b      = (const float*)d_in[12];
  const float* in_proj_w  = (const float*)d_in[13];
  const float* in_proj_b  = (const float*)d_in[14];
  const float* attn_out_w = (const float*)d_in[15];
  const float* attn_out_b = (const float*)d_in[16];
  const float* lin1_w     = (const float*)d_in[17];
  const float* lin1_b     = (const float*)d_in[18];
  const float* lin2_w     = (const float*)d_in[19];
  const float* lin2_b     = (const float*)d_in[20];
  const float* ln1_g      = (const float*)d_in[21];
  const float* ln1_b      = (const float*)d_in[22];
  const float* ln2_g      = (const float*)d_in[23];
  const float* ln2_b      = (const float*)d_in[24];
  const float* out_w      = (const float*)d_in[25];
  const float* out_b      = (const float*)d_in[26];

  float* c1   = symf(g_c1);
  float* c2g  = symf(g_c2g);
  float* c3   = symf(g_c3);
  float* x    = symf(g_x);
  float* qkv  = symf(g_qkv);
  float* part = symf(g_part);
  float* st   = symf(g_stats);
  __half *a1h=symh(g_a1h), *a1l=symh(g_a1l);
  __half *a2h=symh(g_a2h), *a2l=symh(g_a2l);
  __half *col2h=symh(g_col2h), *col2l=symh(g_col2l);
  __half *col3h=symh(g_col3h), *col3l=symh(g_col3l);
  __half *xh=symh(g_xh), *xl=symh(g_xl);
  __half *atth=symh(g_atth), *attl=symh(g_attl);
  __half *hh=symh(g_hh), *hl=symh(g_hl);
  __half *w2=symh(g_w2), *w3=symh(g_w3), *wip=symh(g_wip), *wao=symh(g_wao);
  __half *wl1=symh(g_wl1), *wl2=symh(g_wl2), *wout=symh(g_wout);

  cudaFuncSetAttribute(gemm4<0,0>, cudaFuncAttributeMaxDynamicSharedMemorySize, GEMM4_SMEM);
  cudaFuncSetAttribute(gemm4<1,1>, cudaFuncAttributeMaxDynamicSharedMemorySize, GEMM4_SMEM);
  cudaFuncSetAttribute(gemm4<0,2>, cudaFuncAttributeMaxDynamicSharedMemorySize, GEMM4_SMEM);

  // ---- merged weight conversion ----
  {
    WConvArgs a;
    a.s[0]=(const float4*)cw2;        a.h[0]=(uint4*)w2;   a.n8[0]=80*808/8;
    a.s[1]=(const float4*)cw3;        a.h[1]=(uint4*)w3;   a.n8[1]=800*4080/8;
    a.s[2]=(const float4*)in_proj_w;  a.h[2]=(uint4*)wip;  a.n8[2]=8*2400*800/8;
    a.s[3]=(const float4*)attn_out_w; a.h[3]=(uint4*)wao;  a.n8[3]=8*800*800/8;
    a.s[4]=(const float4*)lin1_w;     a.h[4]=(uint4*)wl1;  a.n8[4]=8*3200*800/8;
    a.s[5]=(const float4*)lin2_w;     a.h[5]=(uint4*)wl2;  a.n8[5]=8*800*3200/8;
    a.s[6]=(const float4*)out_w;      a.h[6]=(uint4*)wout; a.n8[6]=800*800/8;
    wconv_all<<<1184,256>>>(a);
  }

  // ---- patch embedding ----
  conv1_kernel<<<dim3(64,4),128>>>(src, cw1, cb1, c1);
  gn_stats_kernel<<<64,256>>>(c1, st, 8*1800);
  gn1_apply_split<<<CDIV(64*8*450,256),256>>>(c1, a1h, a1l, st, gn1_g, gn1_b);
  im2col2_gather<<<dim3(180,64),256>>>(a1h, a1l, col2h, col2l);
  gemm4<0,2><<<dim3(1,180,2),256,GEMM4_SMEM>>>(col2h, col2l, w2, nullptr, part,
                                               nullptr, nullptr, 11520, 80, 808);
  red_plain<<<CDIV(11520*20,256),256>>>((const float4*)part, cb2, (float4*)c2g, 11520*20, 80, 2);
  gn_stats_kernel<<<64,256>>>(c2g, st, 180*80);
  gn2_apply_split<<<CDIV(11520*20,256),256>>>(c2g, a2h, a2l, st, gn2_g, gn2_b);
  im2col3_gather<<<dim3(18,64),256>>>(a2h, a2l, col3h, col3l);
  gemm4<0,2><<<dim3(7,18,3),256,GEMM4_SMEM>>>(col3h, col3l, w3, nullptr, part,
                                              nullptr, nullptr, 1152, 800, 4080);
  red_plain<<<CDIV(1152*200,256),256>>>((const float4*)part, cb3, (float4*)c3, 1152*200, 800, 3);
  gn_stats_kernel<<<64,256>>>(c3, st, 18*800);
  gn3_pe_kernel<<<CDIV(1152*200,256),256>>>(c3, x, xh, xl, st, gn3_g, gn3_b);

  // ---- transformer layers (split-K=3 on N=800 GEMMs) ----
  for (int i = 0; i < 8; ++i) {
    gemm4<0,0><<<dim3(19,18),256,GEMM4_SMEM>>>(xh, xl,
        wip + (size_t)i*2400*800,
        in_proj_b + (size_t)i*2400, qkv, nullptr, nullptr, 1152, 2400, 800);
    attn_kernel<<<dim3(64,8),128>>>(qkv, atth, attl);
    gemm4<0,2><<<dim3(7,18,3),256,GEMM4_SMEM>>>(atth, attl,
        wao + (size_t)i*800*800,
        nullptr, part, nullptr, nullptr, 1152, 800, 800);
    red_add_ln<<<1152,256>>>(x, xh, xl, part, attn_out_b + (size_t)i*800,
                             ln1_g + (size_t)i*800, ln1_b + (size_t)i*800);
    gemm4<1,1><<<dim3(25,18),256,GEMM4_SMEM>>>(xh, xl,
        wl1 + (size_t)i*3200*800,
        lin1_b + (size_t)i*3200, nullptr, hh, hl, 1152, 3200, 800);
    gemm4<0,2><<<dim3(7,18,3),256,GEMM4_SMEM>>>(hh, hl,
        wl2 + (size_t)i*800*3200,
        nullptr, part, nullptr, nullptr, 1152, 800, 3200);
    red_add_ln<<<1152,256>>>(x, xh, xl, part, lin2_b + (size_t)i*800,
                             ln2_g + (size_t)i*800, ln2_b + (size_t)i*800);
  }

  // ---- output projection (split-K=3 + reduce into d_out) ----
  gemm4<0,2><<<dim3(7,18,3),256,GEMM4_SMEM>>>(xh, xl, wout, nullptr, part,
                                              nullptr, nullptr, 1152, 800, 800);
  red_plain<<<CDIV(1152*200,256),256>>>((const float4*)part, out_b, (float4*)d_out, 1152*200, 800, 3);
}